// round 9
// baseline (speedup 1.0000x reference)
#include <cuda_runtime.h>
#include <cuda_bf16.h>
#include <math.h>
#include <stdint.h>

// Problem dims (fixed)
#define NB 96
#define NQ 96
#define NV 197
#define NT 77
#define ND 768
#define NE 512

__device__ float         g_vtok_f32[(size_t)NB * NV * NE];
__device__ float         g_ttok_f32[(size_t)NQ * NT * NE];
__device__ __nv_bfloat16 g_vtok[(size_t)NB * NV * NE];
__device__ __nv_bfloat16 g_ttok[(size_t)NQ * NT * NE];
// bf16 pre-converted GEMM inputs
__device__ __nv_bfloat16 g_xvb[(size_t)NB * NV * ND];
__device__ __nv_bfloat16 g_xtb[(size_t)NQ * NT * ND];
__device__ __nv_bfloat16 g_wvb[(size_t)NE * ND];
__device__ __nv_bfloat16 g_wtb[(size_t)NE * ND];

__device__ __forceinline__ uint32_t smem_u32(const void* p) {
    uint32_t a;
    asm("{ .reg .u64 t; cvta.to.shared.u64 t, %1; cvt.u32.u64 %0, t; }"
        : "=r"(a) : "l"(p));
    return a;
}
__device__ __forceinline__ void ldmatrix_x4(uint32_t* r, uint32_t addr) {
    asm volatile("ldmatrix.sync.aligned.m8n8.x4.shared.b16 {%0,%1,%2,%3}, [%4];"
        : "=r"(r[0]), "=r"(r[1]), "=r"(r[2]), "=r"(r[3]) : "r"(addr));
}
__device__ __forceinline__ void mma_16816(float* c, const uint32_t* a, const uint32_t* b) {
    asm volatile("mma.sync.aligned.m16n8k16.row.col.f32.bf16.bf16.f32 "
        "{%0,%1,%2,%3}, {%4,%5,%6,%7}, {%8,%9}, {%0,%1,%2,%3};"
        : "+f"(c[0]), "+f"(c[1]), "+f"(c[2]), "+f"(c[3])
        : "r"(a[0]), "r"(a[1]), "r"(a[2]), "r"(a[3]), "r"(b[0]), "r"(b[1]));
}
__device__ __forceinline__ void cp16(uint32_t dst, const void* src, bool pred) {
    int sz = pred ? 16 : 0;
    asm volatile("cp.async.cg.shared.global [%0], [%1], 16, %2;"
        :: "r"(dst), "l"(src), "r"(sz) : "memory");
}
#define CP_COMMIT() asm volatile("cp.async.commit_group;" ::: "memory")
__device__ __forceinline__ uint4 f32x8_bf16(float4 a, float4 b) {
    uint4 r;
    __nv_bfloat162 p;
    p = __float22bfloat162_rn(make_float2(a.x, a.y)); r.x = *(uint32_t*)&p;
    p = __float22bfloat162_rn(make_float2(a.z, a.w)); r.y = *(uint32_t*)&p;
    p = __float22bfloat162_rn(make_float2(b.x, b.y)); r.z = *(uint32_t*)&p;
    p = __float22bfloat162_rn(make_float2(b.z, b.w)); r.w = *(uint32_t*)&p;
    return r;
}

// ===========================================================================
// Convert fp32 inputs -> bf16 operand buffers
// ===========================================================================
#define CSEG0 ((size_t)NB * NV * ND)
#define CSEG1 (CSEG0 + (size_t)NQ * NT * ND)
#define CSEG2 (CSEG1 + (size_t)NE * ND)
#define CSEG3 (CSEG2 + (size_t)NE * ND)

__global__ __launch_bounds__(256) void convert_bf16(
    const float* __restrict__ xv, const float* __restrict__ xt,
    const float* __restrict__ wv, const float* __restrict__ wt)
{
    size_t e = ((size_t)blockIdx.x * 256 + threadIdx.x) * 8;
    if (e >= CSEG3) return;
    const float* src;
    __nv_bfloat16* dst;
    size_t off;
    if (e < CSEG0)      { src = xv; dst = g_xvb; off = e; }
    else if (e < CSEG1) { src = xt; dst = g_xtb; off = e - CSEG0; }
    else if (e < CSEG2) { src = wv; dst = g_wvb; off = e - CSEG1; }
    else                { src = wt; dst = g_wtb; off = e - CSEG2; }
    const float4* p = (const float4*)(src + off);
    *(uint4*)(dst + off) = f32x8_bf16(p[0], p[1]);
}

// ===========================================================================
// cls projections (exact fp32 SIMT), one launch via blockIdx.z
// ===========================================================================
__global__ __launch_bounds__(256) void proj_cls(
    const float* __restrict__ Xv, const float* __restrict__ Wv,
    const float* __restrict__ bv, float* __restrict__ Yv,
    const float* __restrict__ Xt, const float* __restrict__ Wt,
    const float* __restrict__ bt, float* __restrict__ Yt)
{
    const float* X = blockIdx.z ? Xt : Xv;
    const float* W = blockIdx.z ? Wt : Wv;
    const float* bias = blockIdx.z ? bt : bv;
    float* Y = blockIdx.z ? Yt : Yv;
    const int R = NB;

    __shared__ float As[16][68];
    __shared__ float Bs[16][68];
    const int r0 = blockIdx.x * 64, e0 = blockIdx.y * 64;
    const int tid = threadIdx.x;
    const int ty = tid >> 4, tx = tid & 15;
    const int lrow = tid >> 2, lk4 = tid & 3;

    float acc[4][4];
#pragma unroll
    for (int i = 0; i < 4; i++)
#pragma unroll
        for (int j = 0; j < 4; j++) acc[i][j] = 0.f;

    const int r_ld = r0 + lrow;
    const float4 zero4 = make_float4(0.f, 0.f, 0.f, 0.f);

    for (int k0 = 0; k0 < ND; k0 += 16) {
        float4 av = (r_ld < R)
            ? *(const float4*)(X + (size_t)r_ld * ND + k0 + lk4 * 4) : zero4;
        float4 bv4 = *(const float4*)(W + (size_t)(e0 + lrow) * ND + k0 + lk4 * 4);
        __syncthreads();
        As[lk4 * 4 + 0][lrow] = av.x; As[lk4 * 4 + 1][lrow] = av.y;
        As[lk4 * 4 + 2][lrow] = av.z; As[lk4 * 4 + 3][lrow] = av.w;
        Bs[lk4 * 4 + 0][lrow] = bv4.x; Bs[lk4 * 4 + 1][lrow] = bv4.y;
        Bs[lk4 * 4 + 2][lrow] = bv4.z; Bs[lk4 * 4 + 3][lrow] = bv4.w;
        __syncthreads();
#pragma unroll
        for (int kk = 0; kk < 16; kk++) {
            float4 a = *(const float4*)&As[kk][ty * 4];
            float4 b = *(const float4*)&Bs[kk][tx * 4];
            float aa[4] = {a.x, a.y, a.z, a.w};
            float bb[4] = {b.x, b.y, b.z, b.w};
#pragma unroll
            for (int i = 0; i < 4; i++)
#pragma unroll
                for (int j = 0; j < 4; j++)
                    acc[i][j] = fmaf(aa[i], bb[j], acc[i][j]);
        }
    }
#pragma unroll
    for (int i = 0; i < 4; i++) {
        int r = r0 + ty * 4 + i;
        if (r < R) {
#pragma unroll
            for (int j = 0; j < 4; j++) {
                int e = e0 + tx * 4 + j;
                Y[(size_t)r * NE + e] = acc[i][j] + bias[e];
            }
        }
    }
}

// ===========================================================================
// Token projection v2 (unchanged from R8)
// ===========================================================================
#define PPITCH 144
#define PBOFF  (128 * PPITCH)
#define PSTAGE (2 * PBOFF)
#define VIS_BX 148
#define TEX_BX 58

__global__ __launch_bounds__(256, 2) void proj_mma2(
    const float* __restrict__ bias_v, const float* __restrict__ bias_t)
{
    const int z = blockIdx.z;
    if (z == 1 && blockIdx.x >= TEX_BX) return;
    const int R = z ? (NQ * NT) : (NB * NV);
    const uint4* Xb = (const uint4*)(z ? g_xtb : g_xvb);
    const uint4* Wb = (const uint4*)(z ? g_wtb : g_wvb);
    const float* bias = z ? bias_t : bias_v;
    float* Y = z ? g_ttok_f32 : g_vtok_f32;

    extern __shared__ __align__(16) char psm[];
    const uint32_t st0 = smem_u32(psm), st1 = st0 + PSTAGE;

    const int tid = threadIdx.x, wid = tid >> 5, lane = tid & 31;
    const int r0 = blockIdx.x * 128, e0 = blockIdx.y * 128;
    const int mrow = (wid & 3) * 32, ncol = (wid >> 2) * 64;

    const uint32_t aoff = (uint32_t)(mrow + (lane & 7) + ((lane >> 3) & 1) * 8) * PPITCH
                        + (uint32_t)(lane >> 4) * 16;
    const uint32_t boff = PBOFF
                        + (uint32_t)(ncol + (lane & 7) + ((lane >> 4) << 3)) * PPITCH
                        + (uint32_t)((lane >> 3) & 1) * 16;

    float c[2][8][4];
#pragma unroll
    for (int mi = 0; mi < 2; mi++)
#pragma unroll
        for (int ni = 0; ni < 8; ni++)
#pragma unroll
            for (int j = 0; j < 4; j++) c[mi][ni][j] = 0.f;

    auto issue = [&](int ch, uint32_t sbase) {
        const int k4 = ch * 8;
#pragma unroll
        for (int it = 0; it < 8; it++) {
            int slot = it * 256 + tid, row = slot >> 3, seg = slot & 7;
            if (row < 128) {
                bool ok = (r0 + row) < R;
                const uint4* src = Xb + (ok ? (size_t)(r0 + row) * 96 : 0) + k4 + seg;
                cp16(sbase + (uint32_t)(row * PPITCH + seg * 16), src, ok);
            } else {
                int wr = row - 128;
                const uint4* src = Wb + (size_t)(e0 + wr) * 96 + k4 + seg;
                cp16(sbase + (uint32_t)(PBOFF + wr * PPITCH + seg * 16), src, true);
            }
        }
    };

    issue(0, st0); CP_COMMIT();
    issue(1, st1); CP_COMMIT();

    for (int ch = 0; ch < 12; ch++) {
        if (ch == 11) asm volatile("cp.async.wait_group 0;" ::: "memory");
        else          asm volatile("cp.async.wait_group 1;" ::: "memory");
        __syncthreads();

        const uint32_t sb = (ch & 1) ? st1 : st0;
        const uint32_t aa = sb + aoff, ba = sb + boff;
#pragma unroll
        for (int ks = 0; ks < 4; ks++) {
            uint32_t af[2][4], bf[16];
#pragma unroll
            for (int mi = 0; mi < 2; mi++)
                ldmatrix_x4(af[mi], aa + mi * (16 * PPITCH) + ks * 32);
#pragma unroll
            for (int nn = 0; nn < 4; nn++)
                ldmatrix_x4(bf + nn * 4, ba + nn * (16 * PPITCH) + ks * 32);
#pragma unroll
            for (int mi = 0; mi < 2; mi++)
#pragma unroll
                for (int ni = 0; ni < 8; ni++)
                    mma_16816(c[mi][ni], af[mi], bf + ni * 2);
        }
        __syncthreads();
        if (ch + 2 < 12) { issue(ch + 2, sb); CP_COMMIT(); }
    }

#pragma unroll
    for (int mi = 0; mi < 2; mi++) {
        int rr = r0 + mrow + mi * 16 + (lane >> 2);
        if (rr < R) {
#pragma unroll
            for (int ni = 0; ni < 8; ni++) {
                int e = e0 + ncol + ni * 8 + ((lane & 3) << 1);
                float2 o;
                o.x = c[mi][ni][0] + bias[e];
                o.y = c[mi][ni][1] + bias[e + 1];
                *(float2*)(Y + (size_t)rr * NE + e) = o;
                o.x = c[mi][ni][2] + bias[e];
                o.y = c[mi][ni][3] + bias[e + 1];
                *(float2*)(Y + (size_t)(rr + 8) * NE + e) = o;
            }
        }
    }
}

// ===========================================================================
// L2-normalize rows (fp32 in), write bf16 operand buffers
// ===========================================================================
__global__ __launch_bounds__(256) void l2norm_rows()
{
    const int NROWS_V = NB * NV;
    const int NROWS = NROWS_V + NQ * NT;
    int row = blockIdx.x * 8 + (threadIdx.x >> 5);
    int lane = threadIdx.x & 31;
    if (row >= NROWS) return;
    const float* src;
    __nv_bfloat16* dst;
    if (row < NROWS_V) {
        src = g_vtok_f32 + (size_t)row * NE;
        dst = g_vtok + (size_t)row * NE;
    } else {
        src = g_ttok_f32 + (size_t)(row - NROWS_V) * NE;
        dst = g_ttok + (size_t)(row - NROWS_V) * NE;
    }
    const float4* p4 = (const float4*)src;
    float s = 0.f;
#pragma unroll
    for (int i = lane; i < NE / 4; i += 32) {
        float4 v = p4[i];
        s += v.x * v.x + v.y * v.y + v.z * v.z + v.w * v.w;
    }
#pragma unroll
    for (int off = 16; off > 0; off >>= 1)
        s += __shfl_xor_sync(0xffffffffu, s, off);
    float inv = 1.f / fmaxf(sqrtf(s), 1e-12f);
    __nv_bfloat162* d2 = (__nv_bfloat162*)dst;
#pragma unroll
    for (int i = lane; i < NE / 4; i += 32) {
        float4 v = p4[i];
        d2[2 * i]     = __float22bfloat162_rn(make_float2(v.x * inv, v.y * inv));
        d2[2 * i + 1] = __float22bfloat162_rn(make_float2(v.z * inv, v.w * inv));
    }
}

// ===========================================================================
// Stage 2: M=208 (5% pad) with asymmetric warp m-tiles, SMSP-balanced.
//   Per q-group: 13 x 16-row tiles over 8 m-warps (five 32-row, three 16-row).
//   q0 tile counts by w&7: {2,2,2,2,2,1,1,1}; q1: {2,2,2,2,1,2,1,1}
//   -> per-SMSP m-tile totals (7,7,6,6) instead of uniform 8.
// ===========================================================================
#define APITCH 144
#define MROWS  208
#define BOFF2  (MROWS * APITCH)                // 29952
#define STAGE  (BOFF2 + 160 * APITCH)         // 52992
#define SMEM_DYN (3 * STAGE)                  // 158976
#define NINF   (-INFINITY)

__global__ __launch_bounds__(512, 1) void stage2(
    const int* __restrict__ text_length,
    float* __restrict__ t2v, float* __restrict__ v2t)
{
    extern __shared__ __align__(16) char dsm[];
    __shared__ float s_colmax[8][164];
    __shared__ float s_vsum[16];
    __shared__ float s_tred[256];

    const int tid = threadIdx.x;
    const int wid = tid >> 5, lane = tid & 31;
    const int qb = blockIdx.x, b = blockIdx.y;

    const int len0 = text_length[2 * qb];
    const int len1 = text_length[2 * qb + 1];

    const uint4* Va  = (const uint4*)(g_vtok + (size_t)b * NV * NE);
    const uint4* Tt0 = (const uint4*)(g_ttok + (size_t)(2 * qb) * NT * NE);
    const uint4* Tt1 = (const uint4*)(g_ttok + (size_t)(2 * qb + 1) * NT * NE);

    const uint32_t st[3] = { smem_u32(dsm), smem_u32(dsm) + STAGE,
                             smem_u32(dsm) + 2 * STAGE };

    const int w8  = wid & 7;
    const int myq = wid >> 3;
    const int ncol = myq * 80;

    // asymmetric m-tile assignment (warp-uniform)
    int mcnt, moff;
    if (myq == 0) {
        mcnt = (w8 < 5) ? 2 : 1;
        moff = (w8 < 5) ? w8 * 32 : 160 + (w8 - 5) * 16;
    } else {
        mcnt = (w8 == 4 || w8 >= 6) ? 1 : 2;
        if (w8 < 4)       moff = w8 * 32;
        else if (w8 == 4) moff = 128;
        else if (w8 == 5) moff = 144;
        else              moff = 176 + (w8 - 6) * 16;
    }

    const uint32_t aoff = (uint32_t)(moff + (lane & 7) + ((lane >> 3) & 1) * 8) * APITCH
                        + (uint32_t)(lane >> 4) * 16;
    const uint32_t boff = BOFF2
                        + (uint32_t)(ncol + (lane & 7) + ((lane >> 4) << 3)) * APITCH
                        + (uint32_t)((lane >> 3) & 1) * 16;

    float c[2][10][4];
#pragma unroll
    for (int mi = 0; mi < 2; mi++)
#pragma unroll
        for (int ni = 0; ni < 10; ni++)
#pragma unroll
            for (int j = 0; j < 4; j++) c[mi][ni][j] = 0.f;

    auto issue = [&](int ch, uint32_t sbase) {
        const int k4 = ch * 8;
#pragma unroll
        for (int it = 0; it < 4; it++) {           // A: 208 rows x 8 segs = 1664
            int slot = it * 512 + tid;
            if (slot < MROWS * 8) {
                int row = slot >> 3, seg = slot & 7;
                bool ok = row < NV;
                const uint4* src = Va + (ok ? row * 64 : 0) + k4 + seg;
                cp16(sbase + (uint32_t)(row * APITCH + seg * 16), src, ok);
            }
        }
#pragma unroll
        for (int it = 0; it < 3; it++) {           // B: 160 rows x 8 = 1280
            int slot = it * 512 + tid;
            if (slot < 1280) {
                int rbb = slot >> 3, seg = slot & 7;
                int trow = (rbb < 80) ? rbb : rbb - 80;
                bool ok = trow < NT;
                const uint4* base = (rbb < 80) ? Tt0 : Tt1;
                const uint4* src = base + (ok ? trow * 64 : 0) + k4 + seg;
                cp16(sbase + (uint32_t)(BOFF2 + rbb * APITCH + seg * 16), src, ok);
            }
        }
    };

    issue(0, st[0]); CP_COMMIT();
    issue(1, st[1]); CP_COMMIT();
    issue(2, st[2]); CP_COMMIT();

    for (int ch = 0; ch < 8; ch++) {
        if (ch < 6)       asm volatile("cp.async.wait_group 2;" ::: "memory");
        else if (ch == 6) asm volatile("cp.async.wait_group 1;" ::: "memory");
        else              asm volatile("cp.async.wait_group 0;" ::: "memory");
        __syncthreads();

        const uint32_t sb = st[ch % 3];
        const uint32_t aa = sb + aoff, ba = sb + boff;
#pragma unroll
        for (int ks = 0; ks < 4; ks++) {
            uint32_t af[2][4], bf[20];
            ldmatrix_x4(af[0], aa + ks * 32);
            if (mcnt == 2) ldmatrix_x4(af[1], aa + 16 * APITCH + ks * 32);
#pragma unroll
            for (int nn = 0; nn < 5; nn++)
                ldmatrix_x4(bf + nn * 4, ba + nn * (16 * APITCH) + ks * 32);
#pragma unroll
            for (int ni = 0; ni < 10; ni++)
                mma_16816(c[0][ni], af[0], bf + ni * 2);
            if (mcnt == 2) {
#pragma unroll
                for (int ni = 0; ni < 10; ni++)
                    mma_16816(c[1][ni], af[1], bf + ni * 2);
            }
        }
        __syncthreads();
        if (ch + 3 < 8) { issue(ch + 3, sb); CP_COMMIT(); }
    }

    // ---- register/shfl epilogue ----
    const int mylen = myq ? len1 : len0;
    const int rb = moff + (lane >> 2);

    float rowmax[2][2] = {{NINF, NINF}, {NINF, NINF}};
    float colmax[10][2];
#pragma unroll
    for (int ni = 0; ni < 10; ni++) { colmax[ni][0] = NINF; colmax[ni][1] = NINF; }

    for (int mi = 0; mi < mcnt; mi++) {
        int r0 = rb + mi * 16;
        bool v0 = r0 < NV, v8 = (r0 + 8) < NV;
#pragma unroll
        for (int ni = 0; ni < 10; ni++) {
            int tl = ni * 8 + ((lane & 3) << 1);
            float* cf = c[mi][ni];
            float m0 = (tl     < mylen) ? cf[0] : ((tl     < NT) ? 0.f : NINF);
            float m1 = (tl + 1 < mylen) ? cf[1] : ((tl + 1 < NT) ? 0.f : NINF);
            float m2 = (tl     < mylen) ? cf[2] : ((tl     < NT) ? 0.f : NINF);
            float m3 = (tl + 1 < mylen) ? cf[3] : ((tl + 1 < NT) ? 0.f : NINF);
            rowmax[mi][0] = fmaxf(rowmax[mi][0], fmaxf(m0, m1));
            rowmax[mi][1] = fmaxf(rowmax[mi][1], fmaxf(m2, m3));
            colmax[ni][0] = fmaxf(colmax[ni][0],
                fmaxf(v0 ? cf[0] : NINF, v8 ? cf[2] : NINF));
            colmax[ni][1] = fmaxf(colmax[ni][1],
                fmaxf(v0 ? cf[1] : NINF, v8 ? cf[3] : NINF));
        }
    }

#pragma unroll
    for (int mi = 0; mi < 2; mi++)
#pragma unroll
        for (int h = 0; h < 2; h++) {
            float r = rowmax[mi][h];
            r = fmaxf(r, __shfl_xor_sync(0xffffffffu, r, 1));
            r = fmaxf(r, __shfl_xor_sync(0xffffffffu, r, 2));
            rowmax[mi][h] = r;
        }
    float rowsum = 0.f;
    for (int mi = 0; mi < mcnt; mi++) {
        int r0 = rb + mi * 16;
        if (r0 < NV)     rowsum += rowmax[mi][0];
        if (r0 + 8 < NV) rowsum += rowmax[mi][1];
    }
    rowsum += __shfl_xor_sync(0xffffffffu, rowsum, 4);
    rowsum += __shfl_xor_sync(0xffffffffu, rowsum, 8);
    rowsum += __shfl_xor_sync(0xffffffffu, rowsum, 16);
    if (lane == 0) s_vsum[wid] = rowsum;

#pragma unroll
    for (int ni = 0; ni < 10; ni++)
#pragma unroll
        for (int h = 0; h < 2; h++) {
            float r = colmax[ni][h];
            r = fmaxf(r, __shfl_xor_sync(0xffffffffu, r, 4));
            r = fmaxf(r, __shfl_xor_sync(0xffffffffu, r, 8));
            r = fmaxf(r, __shfl_xor_sync(0xffffffffu, r, 16));
            colmax[ni][h] = r;
        }
    if (lane < 4) {
#pragma unroll
        for (int ni = 0; ni < 10; ni++) {
            int cc = ncol + ni * 8 + (lane << 1);
            s_colmax[w8][cc]     = colmax[ni][0];
            s_colmax[w8][cc + 1] = colmax[ni][1];
        }
    }
    __syncthreads();

    if (tid < 256) {
        int qq = tid >> 7, cl = tid & 127;
        float val = 0.f;
        if (cl < 80) {
            float cm = NINF;
#pragma unroll
            for (int w = 0; w < 8; w++) cm = fmaxf(cm, s_colmax[w][qq * 80 + cl]);
            int len = qq ? len1 : len0;
            val = (cl < len) ? cm : 0.f;
        }
        s_tred[tid] = val;
    }
    __syncthreads();
#pragma unroll
    for (int s = 64; s > 0; s >>= 1) {
        if (tid < 256 && (tid & 127) < s) s_tred[tid] += s_tred[tid + s];
        __syncthreads();
    }
    if (tid == 0) {
        float v0s = 0.f, v1s = 0.f;
#pragma unroll
        for (int w = 0; w < 8; w++) { v0s += s_vsum[w]; v1s += s_vsum[8 + w]; }
        t2v[b * NQ + 2 * qb]     = s_tred[0]   / (float)len0;
        t2v[b * NQ + 2 * qb + 1] = s_tred[128] / (float)len1;
        v2t[b * NQ + 2 * qb]     = v0s / (float)NV;
        v2t[b * NQ + 2 * qb + 1] = v1s / (float)NV;
    }
}

// ===========================================================================
extern "C" void kernel_launch(void* const* d_in, const int* in_sizes, int n_in,
                              void* d_out, int out_size)
{
    const float* visual_cls     = (const float*)d_in[0];
    const float* visual_tokens  = (const float*)d_in[1];
    const float* textual_cls    = (const float*)d_in[2];
    const float* textual_tokens = (const float*)d_in[3];
    const float* Wv_cls = (const float*)d_in[4];
    const float* bv_cls = (const float*)d_in[5];
    const float* Wt_cls = (const float*)d_in[6];
    const float* bt_cls = (const float*)d_in[7];
    const float* Wv_tok = (const float*)d_in[8];
    const float* bv_tok = (const float*)d_in[9];
    const float* Wt_tok = (const float*)d_in[10];
    const float* bt_tok = (const float*)d_in[11];
    const int*   text_length = (const int*)d_in[12];

    float* out = (float*)d_out;
    float* o_vcls = out;
    float* o_tcls = out + NB * NE;
    float* o_t2v  = out + 2 * NB * NE;
    float* o_v2t  = o_t2v + NB * NQ;

    {
        size_t n8 = CSEG3 / 8;
        int blocks = (int)((n8 + 255) / 256);
        convert_bf16<<<blocks, 256>>>(visual_tokens, textual_tokens, Wv_tok, Wt_tok);
    }

    proj_cls<<<dim3(2, 8, 2), 256>>>(visual_cls, Wv_cls, bv_cls, o_vcls,
                                     textual_cls, Wt_cls, bt_cls, o_tcls);

    cudaFuncSetAttribute(proj_mma2, cudaFuncAttributeMaxDynamicSharedMemorySize,
                         2 * PSTAGE);
    proj_mma2<<<dim3(VIS_BX, 4, 2), 256, 2 * PSTAGE>>>(bv_tok, bt_tok);

    l2norm_rows<<<(NB * NV + NQ * NT + 7) / 8, 256>>>();

    cudaFuncSetAttribute(stage2, cudaFuncAttributeMaxDynamicSharedMemorySize, SMEM_DYN);
    stage2<<<dim3(NQ / 2, NB), 512, SMEM_DYN>>>(text_length, o_t2v, o_v2t);
}

// round 11
// speedup vs baseline: 4.1440x; 4.1440x over previous
#include <cuda_runtime.h>
#include <cuda_bf16.h>
#include <math.h>
#include <stdint.h>

// Problem dims (fixed)
#define NB 96
#define NQ 96
#define NV 197
#define NT 77
#define ND 768
#define NE 512

__device__ float         g_vtok_f32[(size_t)NB * NV * NE];
__device__ float         g_ttok_f32[(size_t)NQ * NT * NE];
__device__ __nv_bfloat16 g_vtok[(size_t)NB * NV * NE];
__device__ __nv_bfloat16 g_ttok[(size_t)NQ * NT * NE];
// bf16 pre-converted GEMM inputs
__device__ __nv_bfloat16 g_xvb[(size_t)NB * NV * ND];
__device__ __nv_bfloat16 g_xtb[(size_t)NQ * NT * ND];
__device__ __nv_bfloat16 g_wvb[(size_t)NE * ND];
__device__ __nv_bfloat16 g_wtb[(size_t)NE * ND];

__device__ __forceinline__ uint32_t smem_u32(const void* p) {
    uint32_t a;
    asm("{ .reg .u64 t; cvta.to.shared.u64 t, %1; cvt.u32.u64 %0, t; }"
        : "=r"(a) : "l"(p));
    return a;
}
__device__ __forceinline__ void ldmatrix_x4(uint32_t* r, uint32_t addr) {
    asm volatile("ldmatrix.sync.aligned.m8n8.x4.shared.b16 {%0,%1,%2,%3}, [%4];"
        : "=r"(r[0]), "=r"(r[1]), "=r"(r[2]), "=r"(r[3]) : "r"(addr));
}
__device__ __forceinline__ void mma_16816(float* c, const uint32_t* a, const uint32_t* b) {
    asm volatile("mma.sync.aligned.m16n8k16.row.col.f32.bf16.bf16.f32 "
        "{%0,%1,%2,%3}, {%4,%5,%6,%7}, {%8,%9}, {%0,%1,%2,%3};"
        : "+f"(c[0]), "+f"(c[1]), "+f"(c[2]), "+f"(c[3])
        : "r"(a[0]), "r"(a[1]), "r"(a[2]), "r"(a[3]), "r"(b[0]), "r"(b[1]));
}
__device__ __forceinline__ void cp16(uint32_t dst, const void* src, bool pred) {
    int sz = pred ? 16 : 0;
    asm volatile("cp.async.cg.shared.global [%0], [%1], 16, %2;"
        :: "r"(dst), "l"(src), "r"(sz) : "memory");
}
#define CP_COMMIT() asm volatile("cp.async.commit_group;" ::: "memory")
__device__ __forceinline__ uint4 f32x8_bf16(float4 a, float4 b) {
    uint4 r;
    __nv_bfloat162 p;
    p = __float22bfloat162_rn(make_float2(a.x, a.y)); r.x = *(uint32_t*)&p;
    p = __float22bfloat162_rn(make_float2(a.z, a.w)); r.y = *(uint32_t*)&p;
    p = __float22bfloat162_rn(make_float2(b.x, b.y)); r.z = *(uint32_t*)&p;
    p = __float22bfloat162_rn(make_float2(b.z, b.w)); r.w = *(uint32_t*)&p;
    return r;
}

// ===========================================================================
// Convert fp32 inputs -> bf16 operand buffers
// ===========================================================================
#define CSEG0 ((size_t)NB * NV * ND)
#define CSEG1 (CSEG0 + (size_t)NQ * NT * ND)
#define CSEG2 (CSEG1 + (size_t)NE * ND)
#define CSEG3 (CSEG2 + (size_t)NE * ND)

__global__ __launch_bounds__(256) void convert_bf16(
    const float* __restrict__ xv, const float* __restrict__ xt,
    const float* __restrict__ wv, const float* __restrict__ wt)
{
    size_t e = ((size_t)blockIdx.x * 256 + threadIdx.x) * 8;
    if (e >= CSEG3) return;
    const float* src;
    __nv_bfloat16* dst;
    size_t off;
    if (e < CSEG0)      { src = xv; dst = g_xvb; off = e; }
    else if (e < CSEG1) { src = xt; dst = g_xtb; off = e - CSEG0; }
    else if (e < CSEG2) { src = wv; dst = g_wvb; off = e - CSEG1; }
    else                { src = wt; dst = g_wtb; off = e - CSEG2; }
    const float4* p = (const float4*)(src + off);
    *(uint4*)(dst + off) = f32x8_bf16(p[0], p[1]);
}

// ===========================================================================
// cls projections (exact fp32 SIMT), one launch via blockIdx.z
// ===========================================================================
__global__ __launch_bounds__(256) void proj_cls(
    const float* __restrict__ Xv, const float* __restrict__ Wv,
    const float* __restrict__ bv, float* __restrict__ Yv,
    const float* __restrict__ Xt, const float* __restrict__ Wt,
    const float* __restrict__ bt, float* __restrict__ Yt)
{
    const float* X = blockIdx.z ? Xt : Xv;
    const float* W = blockIdx.z ? Wt : Wv;
    const float* bias = blockIdx.z ? bt : bv;
    float* Y = blockIdx.z ? Yt : Yv;
    const int R = NB;

    __shared__ float As[16][68];
    __shared__ float Bs[16][68];
    const int r0 = blockIdx.x * 64, e0 = blockIdx.y * 64;
    const int tid = threadIdx.x;
    const int ty = tid >> 4, tx = tid & 15;
    const int lrow = tid >> 2, lk4 = tid & 3;

    float acc[4][4];
#pragma unroll
    for (int i = 0; i < 4; i++)
#pragma unroll
        for (int j = 0; j < 4; j++) acc[i][j] = 0.f;

    const int r_ld = r0 + lrow;
    const float4 zero4 = make_float4(0.f, 0.f, 0.f, 0.f);

    for (int k0 = 0; k0 < ND; k0 += 16) {
        float4 av = (r_ld < R)
            ? *(const float4*)(X + (size_t)r_ld * ND + k0 + lk4 * 4) : zero4;
        float4 bv4 = *(const float4*)(W + (size_t)(e0 + lrow) * ND + k0 + lk4 * 4);
        __syncthreads();
        As[lk4 * 4 + 0][lrow] = av.x; As[lk4 * 4 + 1][lrow] = av.y;
        As[lk4 * 4 + 2][lrow] = av.z; As[lk4 * 4 + 3][lrow] = av.w;
        Bs[lk4 * 4 + 0][lrow] = bv4.x; Bs[lk4 * 4 + 1][lrow] = bv4.y;
        Bs[lk4 * 4 + 2][lrow] = bv4.z; Bs[lk4 * 4 + 3][lrow] = bv4.w;
        __syncthreads();
#pragma unroll
        for (int kk = 0; kk < 16; kk++) {
            float4 a = *(const float4*)&As[kk][ty * 4];
            float4 b = *(const float4*)&Bs[kk][tx * 4];
            float aa[4] = {a.x, a.y, a.z, a.w};
            float bb[4] = {b.x, b.y, b.z, b.w};
#pragma unroll
            for (int i = 0; i < 4; i++)
#pragma unroll
                for (int j = 0; j < 4; j++)
                    acc[i][j] = fmaf(aa[i], bb[j], acc[i][j]);
        }
    }
#pragma unroll
    for (int i = 0; i < 4; i++) {
        int r = r0 + ty * 4 + i;
        if (r < R) {
#pragma unroll
            for (int j = 0; j < 4; j++) {
                int e = e0 + tx * 4 + j;
                Y[(size_t)r * NE + e] = acc[i][j] + bias[e];
            }
        }
    }
}

// ===========================================================================
// Token projection v2 (unchanged)
// ===========================================================================
#define PPITCH 144
#define PBOFF  (128 * PPITCH)
#define PSTAGE (2 * PBOFF)
#define VIS_BX 148
#define TEX_BX 58

__global__ __launch_bounds__(256, 2) void proj_mma2(
    const float* __restrict__ bias_v, const float* __restrict__ bias_t)
{
    const int z = blockIdx.z;
    if (z == 1 && blockIdx.x >= TEX_BX) return;
    const int R = z ? (NQ * NT) : (NB * NV);
    const uint4* Xb = (const uint4*)(z ? g_xtb : g_xvb);
    const uint4* Wb = (const uint4*)(z ? g_wtb : g_wvb);
    const float* bias = z ? bias_t : bias_v;
    float* Y = z ? g_ttok_f32 : g_vtok_f32;

    extern __shared__ __align__(16) char psm[];
    const uint32_t st0 = smem_u32(psm), st1 = st0 + PSTAGE;

    const int tid = threadIdx.x, wid = tid >> 5, lane = tid & 31;
    const int r0 = blockIdx.x * 128, e0 = blockIdx.y * 128;
    const int mrow = (wid & 3) * 32, ncol = (wid >> 2) * 64;

    const uint32_t aoff = (uint32_t)(mrow + (lane & 7) + ((lane >> 3) & 1) * 8) * PPITCH
                        + (uint32_t)(lane >> 4) * 16;
    const uint32_t boff = PBOFF
                        + (uint32_t)(ncol + (lane & 7) + ((lane >> 4) << 3)) * PPITCH
                        + (uint32_t)((lane >> 3) & 1) * 16;

    float c[2][8][4];
#pragma unroll
    for (int mi = 0; mi < 2; mi++)
#pragma unroll
        for (int ni = 0; ni < 8; ni++)
#pragma unroll
            for (int j = 0; j < 4; j++) c[mi][ni][j] = 0.f;

    auto issue = [&](int ch, uint32_t sbase) {
        const int k4 = ch * 8;
#pragma unroll
        for (int it = 0; it < 8; it++) {
            int slot = it * 256 + tid, row = slot >> 3, seg = slot & 7;
            if (row < 128) {
                bool ok = (r0 + row) < R;
                const uint4* src = Xb + (ok ? (size_t)(r0 + row) * 96 : 0) + k4 + seg;
                cp16(sbase + (uint32_t)(row * PPITCH + seg * 16), src, ok);
            } else {
                int wr = row - 128;
                const uint4* src = Wb + (size_t)(e0 + wr) * 96 + k4 + seg;
                cp16(sbase + (uint32_t)(PBOFF + wr * PPITCH + seg * 16), src, true);
            }
        }
    };

    issue(0, st0); CP_COMMIT();
    issue(1, st1); CP_COMMIT();

    for (int ch = 0; ch < 12; ch++) {
        if (ch == 11) asm volatile("cp.async.wait_group 0;" ::: "memory");
        else          asm volatile("cp.async.wait_group 1;" ::: "memory");
        __syncthreads();

        const uint32_t sb = (ch & 1) ? st1 : st0;
        const uint32_t aa = sb + aoff, ba = sb + boff;
#pragma unroll
        for (int ks = 0; ks < 4; ks++) {
            uint32_t af[2][4], bf[16];
#pragma unroll
            for (int mi = 0; mi < 2; mi++)
                ldmatrix_x4(af[mi], aa + mi * (16 * PPITCH) + ks * 32);
#pragma unroll
            for (int nn = 0; nn < 4; nn++)
                ldmatrix_x4(bf + nn * 4, ba + nn * (16 * PPITCH) + ks * 32);
#pragma unroll
            for (int mi = 0; mi < 2; mi++)
#pragma unroll
                for (int ni = 0; ni < 8; ni++)
                    mma_16816(c[mi][ni], af[mi], bf + ni * 2);
        }
        __syncthreads();
        if (ch + 2 < 12) { issue(ch + 2, sb); CP_COMMIT(); }
    }

#pragma unroll
    for (int mi = 0; mi < 2; mi++) {
        int rr = r0 + mrow + mi * 16 + (lane >> 2);
        if (rr < R) {
#pragma unroll
            for (int ni = 0; ni < 8; ni++) {
                int e = e0 + ncol + ni * 8 + ((lane & 3) << 1);
                float2 o;
                o.x = c[mi][ni][0] + bias[e];
                o.y = c[mi][ni][1] + bias[e + 1];
                *(float2*)(Y + (size_t)rr * NE + e) = o;
                o.x = c[mi][ni][2] + bias[e];
                o.y = c[mi][ni][3] + bias[e + 1];
                *(float2*)(Y + (size_t)(rr + 8) * NE + e) = o;
            }
        }
    }
}

// ===========================================================================
// L2-normalize rows (fp32 in), write bf16 operand buffers
// ===========================================================================
__global__ __launch_bounds__(256) void l2norm_rows()
{
    const int NROWS_V = NB * NV;
    const int NROWS = NROWS_V + NQ * NT;
    int row = blockIdx.x * 8 + (threadIdx.x >> 5);
    int lane = threadIdx.x & 31;
    if (row >= NROWS) return;
    const float* src;
    __nv_bfloat16* dst;
    if (row < NROWS_V) {
        src = g_vtok_f32 + (size_t)row * NE;
        dst = g_vtok + (size_t)row * NE;
    } else {
        src = g_ttok_f32 + (size_t)(row - NROWS_V) * NE;
        dst = g_ttok + (size_t)(row - NROWS_V) * NE;
    }
    const float4* p4 = (const float4*)src;
    float s = 0.f;
#pragma unroll
    for (int i = lane; i < NE / 4; i += 32) {
        float4 v = p4[i];
        s += v.x * v.x + v.y * v.y + v.z * v.z + v.w * v.w;
    }
#pragma unroll
    for (int off = 16; off > 0; off >>= 1)
        s += __shfl_xor_sync(0xffffffffu, s, off);
    float inv = 1.f / fmaxf(sqrtf(s), 1e-12f);
    __nv_bfloat162* d2 = (__nv_bfloat162*)dst;
#pragma unroll
    for (int i = lane; i < NE / 4; i += 32) {
        float4 v = p4[i];
        d2[2 * i]     = __float22bfloat162_rn(make_float2(v.x * inv, v.y * inv));
        d2[2 * i + 1] = __float22bfloat162_rn(make_float2(v.z * inv, v.w * inv));
    }
}

// ===========================================================================
// Stage 2: M=208 asymmetric warp m-tiles — ALL accumulator indexing static.
//   q0 tile counts by w&7: {2,2,2,2,2,1,1,1}; q1: {2,2,2,2,1,2,1,1}
// ===========================================================================
#define APITCH 144
#define MROWS  208
#define BOFF2  (MROWS * APITCH)
#define STAGE  (BOFF2 + 160 * APITCH)
#define SMEM_DYN (3 * STAGE)
#define NINF   (-INFINITY)

__global__ __launch_bounds__(512, 1) void stage2(
    const int* __restrict__ text_length,
    float* __restrict__ t2v, float* __restrict__ v2t)
{
    extern __shared__ __align__(16) char dsm[];
    __shared__ float s_colmax[8][164];
    __shared__ float s_vsum[16];
    __shared__ float s_tred[256];

    const int tid = threadIdx.x;
    const int wid = tid >> 5, lane = tid & 31;
    const int qb = blockIdx.x, b = blockIdx.y;

    const int len0 = text_length[2 * qb];
    const int len1 = text_length[2 * qb + 1];

    const uint4* Va  = (const uint4*)(g_vtok + (size_t)b * NV * NE);
    const uint4* Tt0 = (const uint4*)(g_ttok + (size_t)(2 * qb) * NT * NE);
    const uint4* Tt1 = (const uint4*)(g_ttok + (size_t)(2 * qb + 1) * NT * NE);

    const uint32_t st[3] = { smem_u32(dsm), smem_u32(dsm) + STAGE,
                             smem_u32(dsm) + 2 * STAGE };

    const int w8  = wid & 7;
    const int myq = wid >> 3;
    const int ncol = myq * 80;

    // asymmetric m-tile assignment (warp-uniform, computed once)
    int mcnt, moff;
    if (myq == 0) {
        mcnt = (w8 < 5) ? 2 : 1;
        moff = (w8 < 5) ? w8 * 32 : 160 + (w8 - 5) * 16;
    } else {
        mcnt = (w8 == 4 || w8 >= 6) ? 1 : 2;
        if (w8 < 4)       moff = w8 * 32;
        else if (w8 == 4) moff = 128;
        else if (w8 == 5) moff = 144;
        else              moff = 176 + (w8 - 6) * 16;
    }
    const bool has2 = (mcnt == 2);

    const uint32_t aoff = (uint32_t)(moff + (lane & 7) + ((lane >> 3) & 1) * 8) * APITCH
                        + (uint32_t)(lane >> 4) * 16;
    const uint32_t boff = BOFF2
                        + (uint32_t)(ncol + (lane & 7) + ((lane >> 4) << 3)) * APITCH
                        + (uint32_t)((lane >> 3) & 1) * 16;

    float c[2][10][4];
#pragma unroll
    for (int mi = 0; mi < 2; mi++)
#pragma unroll
        for (int ni = 0; ni < 10; ni++)
#pragma unroll
            for (int j = 0; j < 4; j++) c[mi][ni][j] = 0.f;

    auto issue = [&](int ch, uint32_t sbase) {
        const int k4 = ch * 8;
#pragma unroll
        for (int it = 0; it < 4; it++) {           // A: 208 rows x 8 segs = 1664
            int slot = it * 512 + tid;
            if (slot < MROWS * 8) {
                int row = slot >> 3, seg = slot & 7;
                bool ok = row < NV;
                const uint4* src = Va + (ok ? row * 64 : 0) + k4 + seg;
                cp16(sbase + (uint32_t)(row * APITCH + seg * 16), src, ok);
            }
        }
#pragma unroll
        for (int it = 0; it < 3; it++) {           // B: 160 rows x 8 = 1280
            int slot = it * 512 + tid;
            if (slot < 1280) {
                int rbb = slot >> 3, seg = slot & 7;
                int trow = (rbb < 80) ? rbb : rbb - 80;
                bool ok = trow < NT;
                const uint4* base = (rbb < 80) ? Tt0 : Tt1;
                const uint4* src = base + (ok ? trow * 64 : 0) + k4 + seg;
                cp16(sbase + (uint32_t)(BOFF2 + rbb * APITCH + seg * 16), src, ok);
            }
        }
    };

    issue(0, st[0]); CP_COMMIT();
    issue(1, st[1]); CP_COMMIT();
    issue(2, st[2]); CP_COMMIT();

    for (int ch = 0; ch < 8; ch++) {
        if (ch < 6)       asm volatile("cp.async.wait_group 2;" ::: "memory");
        else if (ch == 6) asm volatile("cp.async.wait_group 1;" ::: "memory");
        else              asm volatile("cp.async.wait_group 0;" ::: "memory");
        __syncthreads();

        const uint32_t sb = st[ch % 3];
        const uint32_t aa = sb + aoff, ba = sb + boff;
#pragma unroll
        for (int ks = 0; ks < 4; ks++) {
            uint32_t af[2][4], bf[20];
            ldmatrix_x4(af[0], aa + ks * 32);
            if (has2) ldmatrix_x4(af[1], aa + 16 * APITCH + ks * 32);
#pragma unroll
            for (int nn = 0; nn < 5; nn++)
                ldmatrix_x4(bf + nn * 4, ba + nn * (16 * APITCH) + ks * 32);
#pragma unroll
            for (int ni = 0; ni < 10; ni++)
                mma_16816(c[0][ni], af[0], bf + ni * 2);
            if (has2) {
#pragma unroll
                for (int ni = 0; ni < 10; ni++)
                    mma_16816(c[1][ni], af[1], bf + ni * 2);
            }
        }
        __syncthreads();
        if (ch + 3 < 8) { issue(ch + 3, sb); CP_COMMIT(); }
    }

    // ---- register/shfl epilogue (all static indexing; 'active' predicates) ----
    const int mylen = myq ? len1 : len0;
    const int rb = moff + (lane >> 2);

    float rowmax[2][2] = {{NINF, NINF}, {NINF, NINF}};
    float colmax[10][2];
#pragma unroll
    for (int ni = 0; ni < 10; ni++) { colmax[ni][0] = NINF; colmax[ni][1] = NINF; }

#pragma unroll
    for (int mi = 0; mi < 2; mi++) {
        const bool active = (mi == 0) || has2;
        int r0 = rb + mi * 16;
        bool v0 = active && (r0 < NV), v8 = active && ((r0 + 8) < NV);
#pragma unroll
        for (int ni = 0; ni < 10; ni++) {
            int tl = ni * 8 + ((lane & 3) << 1);
            float* cf = c[mi][ni];
            float m0 = (tl     < mylen) ? cf[0] : ((tl     < NT) ? 0.f : NINF);
            float m1 = (tl + 1 < mylen) ? cf[1] : ((tl + 1 < NT) ? 0.f : NINF);
            float m2 = (tl     < mylen) ? cf[2] : ((tl     < NT) ? 0.f : NINF);
            float m3 = (tl + 1 < mylen) ? cf[3] : ((tl + 1 < NT) ? 0.f : NINF);
            rowmax[mi][0] = fmaxf(rowmax[mi][0], fmaxf(m0, m1));
            rowmax[mi][1] = fmaxf(rowmax[mi][1], fmaxf(m2, m3));
            colmax[ni][0] = fmaxf(colmax[ni][0],
                fmaxf(v0 ? cf[0] : NINF, v8 ? cf[2] : NINF));
            colmax[ni][1] = fmaxf(colmax[ni][1],
                fmaxf(v0 ? cf[1] : NINF, v8 ? cf[3] : NINF));
        }
    }

#pragma unroll
    for (int mi = 0; mi < 2; mi++)
#pragma unroll
        for (int h = 0; h < 2; h++) {
            float r = rowmax[mi][h];
            r = fmaxf(r, __shfl_xor_sync(0xffffffffu, r, 1));
            r = fmaxf(r, __shfl_xor_sync(0xffffffffu, r, 2));
            rowmax[mi][h] = r;
        }
    float rowsum = 0.f;
#pragma unroll
    for (int mi = 0; mi < 2; mi++) {
        const bool active = (mi == 0) || has2;
        int r0 = rb + mi * 16;
        if (active && r0 < NV)       rowsum += rowmax[mi][0];
        if (active && (r0 + 8) < NV) rowsum += rowmax[mi][1];
    }
    rowsum += __shfl_xor_sync(0xffffffffu, rowsum, 4);
    rowsum += __shfl_xor_sync(0xffffffffu, rowsum, 8);
    rowsum += __shfl_xor_sync(0xffffffffu, rowsum, 16);
    if (lane == 0) s_vsum[wid] = rowsum;

#pragma unroll
    for (int ni = 0; ni < 10; ni++)
#pragma unroll
        for (int h = 0; h < 2; h++) {
            float r = colmax[ni][h];
            r = fmaxf(r, __shfl_xor_sync(0xffffffffu, r, 4));
            r = fmaxf(r, __shfl_xor_sync(0xffffffffu, r, 8));
            r = fmaxf(r, __shfl_xor_sync(0xffffffffu, r, 16));
            colmax[ni][h] = r;
        }
    if (lane < 4) {
#pragma unroll
        for (int ni = 0; ni < 10; ni++) {
            int cc = ncol + ni * 8 + (lane << 1);
            s_colmax[w8][cc]     = colmax[ni][0];
            s_colmax[w8][cc + 1] = colmax[ni][1];
        }
    }
    __syncthreads();

    if (tid < 256) {
        int qq = tid >> 7, cl = tid & 127;
        float val = 0.f;
        if (cl < 80) {
            float cm = NINF;
#pragma unroll
            for (int w = 0; w < 8; w++) cm = fmaxf(cm, s_colmax[w][qq * 80 + cl]);
            int len = qq ? len1 : len0;
            val = (cl < len) ? cm : 0.f;
        }
        s_tred[tid] = val;
    }
    __syncthreads();
#pragma unroll
    for (int s = 64; s > 0; s >>= 1) {
        if (tid < 256 && (tid & 127) < s) s_tred[tid] += s_tred[tid + s];
        __syncthreads();
    }
    if (tid == 0) {
        float v0s = 0.f, v1s = 0.f;
#pragma unroll
        for (int w = 0; w < 8; w++) { v0s += s_vsum[w]; v1s += s_vsum[8 + w]; }
        t2v[b * NQ + 2 * qb]     = s_tred[0]   / (float)len0;
        t2v[b * NQ + 2 * qb + 1] = s_tred[128] / (float)len1;
        v2t[b * NQ + 2 * qb]     = v0s / (float)NV;
        v2t[b * NQ + 2 * qb + 1] = v1s / (float)NV;
    }
}

// ===========================================================================
extern "C" void kernel_launch(void* const* d_in, const int* in_sizes, int n_in,
                              void* d_out, int out_size)
{
    const float* visual_cls     = (const float*)d_in[0];
    const float* visual_tokens  = (const float*)d_in[1];
    const float* textual_cls    = (const float*)d_in[2];
    const float* textual_tokens = (const float*)d_in[3];
    const float* Wv_cls = (const float*)d_in[4];
    const float* bv_cls = (const float*)d_in[5];
    const float* Wt_cls = (const float*)d_in[6];
    const float* bt_cls = (const float*)d_in[7];
    const float* Wv_tok = (const float*)d_in[8];
    const float* bv_tok = (const float*)d_in[9];
    const float* Wt_tok = (const float*)d_in[10];
    const float* bt_tok = (const float*)d_in[11];
    const int*   text_length = (const int*)d_in[12];

    float* out = (float*)d_out;
    float* o_vcls = out;
    float* o_tcls = out + NB * NE;
    float* o_t2v  = out + 2 * NB * NE;
    float* o_v2t  = o_t2v + NB * NQ;

    {
        size_t n8 = CSEG3 / 8;
        int blocks = (int)((n8 + 255) / 256);
        convert_bf16<<<blocks, 256>>>(visual_tokens, textual_tokens, Wv_tok, Wt_tok);
    }

    proj_cls<<<dim3(2, 8, 2), 256>>>(visual_cls, Wv_cls, bv_cls, o_vcls,
                                     textual_cls, Wt_cls, bt_cls, o_tcls);

    cudaFuncSetAttribute(proj_mma2, cudaFuncAttributeMaxDynamicSharedMemorySize,
                         2 * PSTAGE);
    proj_mma2<<<dim3(VIS_BX, 4, 2), 256, 2 * PSTAGE>>>(bv_tok, bt_tok);

    l2norm_rows<<<(NB * NV + NQ * NT + 7) / 8, 256>>>();

    cudaFuncSetAttribute(stage2, cudaFuncAttributeMaxDynamicSharedMemorySize, SMEM_DYN);
    stage2<<<dim3(NQ / 2, NB), 512, SMEM_DYN>>>(text_length, o_t2v, o_v2t);
}

// round 12
// speedup vs baseline: 4.1801x; 1.0087x over previous
#include <cuda_runtime.h>
#include <cuda_bf16.h>
#include <math.h>
#include <stdint.h>

// Problem dims (fixed)
#define NB 96
#define NQ 96
#define NV 197
#define NT 77
#define ND 768
#define NE 512

__device__ float         g_vtok_f32[(size_t)NB * NV * NE];
__device__ float         g_ttok_f32[(size_t)NQ * NT * NE];
__device__ __nv_bfloat16 g_vtok[(size_t)NB * NV * NE];
__device__ __nv_bfloat16 g_ttok[(size_t)NQ * NT * NE];
// bf16 pre-converted GEMM inputs
__device__ __nv_bfloat16 g_xvb[(size_t)NB * NV * ND];
__device__ __nv_bfloat16 g_xtb[(size_t)NQ * NT * ND];
__device__ __nv_bfloat16 g_wvb[(size_t)NE * ND];
__device__ __nv_bfloat16 g_wtb[(size_t)NE * ND];

__device__ __forceinline__ uint32_t smem_u32(const void* p) {
    uint32_t a;
    asm("{ .reg .u64 t; cvta.to.shared.u64 t, %1; cvt.u32.u64 %0, t; }"
        : "=r"(a) : "l"(p));
    return a;
}
__device__ __forceinline__ void ldmatrix_x4(uint32_t* r, uint32_t addr) {
    asm volatile("ldmatrix.sync.aligned.m8n8.x4.shared.b16 {%0,%1,%2,%3}, [%4];"
        : "=r"(r[0]), "=r"(r[1]), "=r"(r[2]), "=r"(r[3]) : "r"(addr));
}
__device__ __forceinline__ void mma_16816(float* c, const uint32_t* a, const uint32_t* b) {
    asm volatile("mma.sync.aligned.m16n8k16.row.col.f32.bf16.bf16.f32 "
        "{%0,%1,%2,%3}, {%4,%5,%6,%7}, {%8,%9}, {%0,%1,%2,%3};"
        : "+f"(c[0]), "+f"(c[1]), "+f"(c[2]), "+f"(c[3])
        : "r"(a[0]), "r"(a[1]), "r"(a[2]), "r"(a[3]), "r"(b[0]), "r"(b[1]));
}
__device__ __forceinline__ void cp16(uint32_t dst, const void* src, bool pred) {
    int sz = pred ? 16 : 0;
    asm volatile("cp.async.cg.shared.global [%0], [%1], 16, %2;"
        :: "r"(dst), "l"(src), "r"(sz) : "memory");
}
#define CP_COMMIT() asm volatile("cp.async.commit_group;" ::: "memory")
__device__ __forceinline__ uint4 f32x8_bf16(float4 a, float4 b) {
    uint4 r;
    __nv_bfloat162 p;
    p = __float22bfloat162_rn(make_float2(a.x, a.y)); r.x = *(uint32_t*)&p;
    p = __float22bfloat162_rn(make_float2(a.z, a.w)); r.y = *(uint32_t*)&p;
    p = __float22bfloat162_rn(make_float2(b.x, b.y)); r.z = *(uint32_t*)&p;
    p = __float22bfloat162_rn(make_float2(b.z, b.w)); r.w = *(uint32_t*)&p;
    return r;
}

// ===========================================================================
// Convert fp32 inputs -> bf16 operand buffers
// ===========================================================================
#define CSEG0 ((size_t)NB * NV * ND)
#define CSEG1 (CSEG0 + (size_t)NQ * NT * ND)
#define CSEG2 (CSEG1 + (size_t)NE * ND)
#define CSEG3 (CSEG2 + (size_t)NE * ND)

__global__ __launch_bounds__(256) void convert_bf16(
    const float* __restrict__ xv, const float* __restrict__ xt,
    const float* __restrict__ wv, const float* __restrict__ wt)
{
    size_t e = ((size_t)blockIdx.x * 256 + threadIdx.x) * 8;
    if (e >= CSEG3) return;
    const float* src;
    __nv_bfloat16* dst;
    size_t off;
    if (e < CSEG0)      { src = xv; dst = g_xvb; off = e; }
    else if (e < CSEG1) { src = xt; dst = g_xtb; off = e - CSEG0; }
    else if (e < CSEG2) { src = wv; dst = g_wvb; off = e - CSEG1; }
    else                { src = wt; dst = g_wtb; off = e - CSEG2; }
    const float4* p = (const float4*)(src + off);
    *(uint4*)(dst + off) = f32x8_bf16(p[0], p[1]);
}

// ===========================================================================
// cls projections (exact fp32 SIMT), one launch via blockIdx.z
// ===========================================================================
__global__ __launch_bounds__(256) void proj_cls(
    const float* __restrict__ Xv, const float* __restrict__ Wv,
    const float* __restrict__ bv, float* __restrict__ Yv,
    const float* __restrict__ Xt, const float* __restrict__ Wt,
    const float* __restrict__ bt, float* __restrict__ Yt)
{
    const float* X = blockIdx.z ? Xt : Xv;
    const float* W = blockIdx.z ? Wt : Wv;
    const float* bias = blockIdx.z ? bt : bv;
    float* Y = blockIdx.z ? Yt : Yv;
    const int R = NB;

    __shared__ float As[16][68];
    __shared__ float Bs[16][68];
    const int r0 = blockIdx.x * 64, e0 = blockIdx.y * 64;
    const int tid = threadIdx.x;
    const int ty = tid >> 4, tx = tid & 15;
    const int lrow = tid >> 2, lk4 = tid & 3;

    float acc[4][4];
#pragma unroll
    for (int i = 0; i < 4; i++)
#pragma unroll
        for (int j = 0; j < 4; j++) acc[i][j] = 0.f;

    const int r_ld = r0 + lrow;
    const float4 zero4 = make_float4(0.f, 0.f, 0.f, 0.f);

    for (int k0 = 0; k0 < ND; k0 += 16) {
        float4 av = (r_ld < R)
            ? *(const float4*)(X + (size_t)r_ld * ND + k0 + lk4 * 4) : zero4;
        float4 bv4 = *(const float4*)(W + (size_t)(e0 + lrow) * ND + k0 + lk4 * 4);
        __syncthreads();
        As[lk4 * 4 + 0][lrow] = av.x; As[lk4 * 4 + 1][lrow] = av.y;
        As[lk4 * 4 + 2][lrow] = av.z; As[lk4 * 4 + 3][lrow] = av.w;
        Bs[lk4 * 4 + 0][lrow] = bv4.x; Bs[lk4 * 4 + 1][lrow] = bv4.y;
        Bs[lk4 * 4 + 2][lrow] = bv4.z; Bs[lk4 * 4 + 3][lrow] = bv4.w;
        __syncthreads();
#pragma unroll
        for (int kk = 0; kk < 16; kk++) {
            float4 a = *(const float4*)&As[kk][ty * 4];
            float4 b = *(const float4*)&Bs[kk][tx * 4];
            float aa[4] = {a.x, a.y, a.z, a.w};
            float bb[4] = {b.x, b.y, b.z, b.w};
#pragma unroll
            for (int i = 0; i < 4; i++)
#pragma unroll
                for (int j = 0; j < 4; j++)
                    acc[i][j] = fmaf(aa[i], bb[j], acc[i][j]);
        }
    }
#pragma unroll
    for (int i = 0; i < 4; i++) {
        int r = r0 + ty * 4 + i;
        if (r < R) {
#pragma unroll
            for (int j = 0; j < 4; j++) {
                int e = e0 + tx * 4 + j;
                Y[(size_t)r * NE + e] = acc[i][j] + bias[e];
            }
        }
    }
}

// ===========================================================================
// Token projection v2 (unchanged)
// ===========================================================================
#define PPITCH 144
#define PBOFF  (128 * PPITCH)
#define PSTAGE (2 * PBOFF)
#define VIS_BX 148
#define TEX_BX 58

__global__ __launch_bounds__(256, 2) void proj_mma2(
    const float* __restrict__ bias_v, const float* __restrict__ bias_t)
{
    const int z = blockIdx.z;
    if (z == 1 && blockIdx.x >= TEX_BX) return;
    const int R = z ? (NQ * NT) : (NB * NV);
    const uint4* Xb = (const uint4*)(z ? g_xtb : g_xvb);
    const uint4* Wb = (const uint4*)(z ? g_wtb : g_wvb);
    const float* bias = z ? bias_t : bias_v;
    float* Y = z ? g_ttok_f32 : g_vtok_f32;

    extern __shared__ __align__(16) char psm[];
    const uint32_t st0 = smem_u32(psm), st1 = st0 + PSTAGE;

    const int tid = threadIdx.x, wid = tid >> 5, lane = tid & 31;
    const int r0 = blockIdx.x * 128, e0 = blockIdx.y * 128;
    const int mrow = (wid & 3) * 32, ncol = (wid >> 2) * 64;

    const uint32_t aoff = (uint32_t)(mrow + (lane & 7) + ((lane >> 3) & 1) * 8) * PPITCH
                        + (uint32_t)(lane >> 4) * 16;
    const uint32_t boff = PBOFF
                        + (uint32_t)(ncol + (lane & 7) + ((lane >> 4) << 3)) * PPITCH
                        + (uint32_t)((lane >> 3) & 1) * 16;

    float c[2][8][4];
#pragma unroll
    for (int mi = 0; mi < 2; mi++)
#pragma unroll
        for (int ni = 0; ni < 8; ni++)
#pragma unroll
            for (int j = 0; j < 4; j++) c[mi][ni][j] = 0.f;

    auto issue = [&](int ch, uint32_t sbase) {
        const int k4 = ch * 8;
#pragma unroll
        for (int it = 0; it < 8; it++) {
            int slot = it * 256 + tid, row = slot >> 3, seg = slot & 7;
            if (row < 128) {
                bool ok = (r0 + row) < R;
                const uint4* src = Xb + (ok ? (size_t)(r0 + row) * 96 : 0) + k4 + seg;
                cp16(sbase + (uint32_t)(row * PPITCH + seg * 16), src, ok);
            } else {
                int wr = row - 128;
                const uint4* src = Wb + (size_t)(e0 + wr) * 96 + k4 + seg;
                cp16(sbase + (uint32_t)(PBOFF + wr * PPITCH + seg * 16), src, true);
            }
        }
    };

    issue(0, st0); CP_COMMIT();
    issue(1, st1); CP_COMMIT();

    for (int ch = 0; ch < 12; ch++) {
        if (ch == 11) asm volatile("cp.async.wait_group 0;" ::: "memory");
        else          asm volatile("cp.async.wait_group 1;" ::: "memory");
        __syncthreads();

        const uint32_t sb = (ch & 1) ? st1 : st0;
        const uint32_t aa = sb + aoff, ba = sb + boff;
#pragma unroll
        for (int ks = 0; ks < 4; ks++) {
            uint32_t af[2][4], bf[16];
#pragma unroll
            for (int mi = 0; mi < 2; mi++)
                ldmatrix_x4(af[mi], aa + mi * (16 * PPITCH) + ks * 32);
#pragma unroll
            for (int nn = 0; nn < 4; nn++)
                ldmatrix_x4(bf + nn * 4, ba + nn * (16 * PPITCH) + ks * 32);
#pragma unroll
            for (int mi = 0; mi < 2; mi++)
#pragma unroll
                for (int ni = 0; ni < 8; ni++)
                    mma_16816(c[mi][ni], af[mi], bf + ni * 2);
        }
        __syncthreads();
        if (ch + 2 < 12) { issue(ch + 2, sb); CP_COMMIT(); }
    }

#pragma unroll
    for (int mi = 0; mi < 2; mi++) {
        int rr = r0 + mrow + mi * 16 + (lane >> 2);
        if (rr < R) {
#pragma unroll
            for (int ni = 0; ni < 8; ni++) {
                int e = e0 + ncol + ni * 8 + ((lane & 3) << 1);
                float2 o;
                o.x = c[mi][ni][0] + bias[e];
                o.y = c[mi][ni][1] + bias[e + 1];
                *(float2*)(Y + (size_t)rr * NE + e) = o;
                o.x = c[mi][ni][2] + bias[e];
                o.y = c[mi][ni][3] + bias[e + 1];
                *(float2*)(Y + (size_t)(rr + 8) * NE + e) = o;
            }
        }
    }
}

// ===========================================================================
// L2-normalize rows (fp32 in), write bf16 operand buffers
// ===========================================================================
__global__ __launch_bounds__(256) void l2norm_rows()
{
    const int NROWS_V = NB * NV;
    const int NROWS = NROWS_V + NQ * NT;
    int row = blockIdx.x * 8 + (threadIdx.x >> 5);
    int lane = threadIdx.x & 31;
    if (row >= NROWS) return;
    const float* src;
    __nv_bfloat16* dst;
    if (row < NROWS_V) {
        src = g_vtok_f32 + (size_t)row * NE;
        dst = g_vtok + (size_t)row * NE;
    } else {
        src = g_ttok_f32 + (size_t)(row - NROWS_V) * NE;
        dst = g_ttok + (size_t)(row - NROWS_V) * NE;
    }
    const float4* p4 = (const float4*)src;
    float s = 0.f;
#pragma unroll
    for (int i = lane; i < NE / 4; i += 32) {
        float4 v = p4[i];
        s += v.x * v.x + v.y * v.y + v.z * v.z + v.w * v.w;
    }
#pragma unroll
    for (int off = 16; off > 0; off >>= 1)
        s += __shfl_xor_sync(0xffffffffu, s, off);
    float inv = 1.f / fmaxf(sqrtf(s), 1e-12f);
    __nv_bfloat162* d2 = (__nv_bfloat162*)dst;
#pragma unroll
    for (int i = lane; i < NE / 4; i += 32) {
        float4 v = p4[i];
        d2[2 * i]     = __float22bfloat162_rn(make_float2(v.x * inv, v.y * inv));
        d2[2 * i + 1] = __float22bfloat162_rn(make_float2(v.z * inv, v.w * inv));
    }
}

// ===========================================================================
// Stage 2 v3: one CTA = (b, q). 256 threads, 2 CTAs/SM (occupancy lever).
//   M=208 asymmetric (13 x 16-row tiles over 8 warps: {2,2,2,2,2,1,1,1}),
//   N=80 (1 q), K=512 in 8x64 chunks, 2-stage cp.async.
// ===========================================================================
#define APITCH 144
#define MROWS  208
#define BOFF2  (MROWS * APITCH)                // 29952
#define STAGE  (BOFF2 + 80 * APITCH)          // 41472
#define SMEM_DYN (2 * STAGE)                  // 82944 -> 2 CTAs/SM
#define NINF   (-INFINITY)

__global__ __launch_bounds__(256, 2) void stage2(
    const int* __restrict__ text_length,
    float* __restrict__ t2v, float* __restrict__ v2t)
{
    extern __shared__ __align__(16) char dsm[];
    __shared__ float s_colmax[8][84];
    __shared__ float s_vsum[8];
    __shared__ float s_tred[128];

    const int tid = threadIdx.x;
    const int wid = tid >> 5, lane = tid & 31;
    const int q = blockIdx.x, b = blockIdx.y;

    const int len = text_length[q];

    const uint4* Va = (const uint4*)(g_vtok + (size_t)b * NV * NE);
    const uint4* Tt = (const uint4*)(g_ttok + (size_t)q * NT * NE);

    const uint32_t st0 = smem_u32(dsm), st1 = st0 + STAGE;

    // asymmetric m-tile assignment (warp-uniform)
    const int mcnt = (wid < 5) ? 2 : 1;
    const int moff = (wid < 5) ? wid * 32 : 160 + (wid - 5) * 16;
    const bool has2 = (mcnt == 2);

    const uint32_t aoff = (uint32_t)(moff + (lane & 7) + ((lane >> 3) & 1) * 8) * APITCH
                        + (uint32_t)(lane >> 4) * 16;
    const uint32_t boff = BOFF2
                        + (uint32_t)((lane & 7) + ((lane >> 4) << 3)) * APITCH
                        + (uint32_t)((lane >> 3) & 1) * 16;

    float c[2][10][4];
#pragma unroll
    for (int mi = 0; mi < 2; mi++)
#pragma unroll
        for (int ni = 0; ni < 10; ni++)
#pragma unroll
            for (int j = 0; j < 4; j++) c[mi][ni][j] = 0.f;

    auto issue = [&](int ch, uint32_t sbase) {
        const int k4 = ch * 8;
#pragma unroll
        for (int it = 0; it < 7; it++) {           // A: 208 rows x 8 = 1664 slots
            int slot = it * 256 + tid;
            if (slot < MROWS * 8) {
                int row = slot >> 3, seg = slot & 7;
                bool ok = row < NV;
                const uint4* src = Va + (ok ? row * 64 : 0) + k4 + seg;
                cp16(sbase + (uint32_t)(row * APITCH + seg * 16), src, ok);
            }
        }
#pragma unroll
        for (int it = 0; it < 3; it++) {           // B: 80 rows x 8 = 640 slots
            int slot = it * 256 + tid;
            if (slot < 640) {
                int row = slot >> 3, seg = slot & 7;
                bool ok = row < NT;
                const uint4* src = Tt + (ok ? row * 64 : 0) + k4 + seg;
                cp16(sbase + (uint32_t)(BOFF2 + row * APITCH + seg * 16), src, ok);
            }
        }
    };

    issue(0, st0); CP_COMMIT();
    issue(1, st1); CP_COMMIT();

    for (int ch = 0; ch < 8; ch++) {
        if (ch == 7) asm volatile("cp.async.wait_group 0;" ::: "memory");
        else         asm volatile("cp.async.wait_group 1;" ::: "memory");
        __syncthreads();

        const uint32_t sb = (ch & 1) ? st1 : st0;
        const uint32_t aa = sb + aoff, ba = sb + boff;
#pragma unroll
        for (int ks = 0; ks < 4; ks++) {
            uint32_t af[2][4], bf[20];
            ldmatrix_x4(af[0], aa + ks * 32);
            if (has2) ldmatrix_x4(af[1], aa + 16 * APITCH + ks * 32);
#pragma unroll
            for (int nn = 0; nn < 5; nn++)
                ldmatrix_x4(bf + nn * 4, ba + nn * (16 * APITCH) + ks * 32);
#pragma unroll
            for (int ni = 0; ni < 10; ni++)
                mma_16816(c[0][ni], af[0], bf + ni * 2);
            if (has2) {
#pragma unroll
                for (int ni = 0; ni < 10; ni++)
                    mma_16816(c[1][ni], af[1], bf + ni * 2);
            }
        }
        __syncthreads();
        if (ch + 2 < 8) { issue(ch + 2, sb); CP_COMMIT(); }
    }

    // ---- register/shfl epilogue (static indexing, 'active' predicates) ----
    const int rb = moff + (lane >> 2);

    float rowmax[2][2] = {{NINF, NINF}, {NINF, NINF}};
    float colmax[10][2];
#pragma unroll
    for (int ni = 0; ni < 10; ni++) { colmax[ni][0] = NINF; colmax[ni][1] = NINF; }

#pragma unroll
    for (int mi = 0; mi < 2; mi++) {
        const bool active = (mi == 0) || has2;
        int r0 = rb + mi * 16;
        bool v0 = active && (r0 < NV), v8 = active && ((r0 + 8) < NV);
#pragma unroll
        for (int ni = 0; ni < 10; ni++) {
            int tl = ni * 8 + ((lane & 3) << 1);
            float* cf = c[mi][ni];
            float m0 = (tl     < len) ? cf[0] : ((tl     < NT) ? 0.f : NINF);
            float m1 = (tl + 1 < len) ? cf[1] : ((tl + 1 < NT) ? 0.f : NINF);
            float m2 = (tl     < len) ? cf[2] : ((tl     < NT) ? 0.f : NINF);
            float m3 = (tl + 1 < len) ? cf[3] : ((tl + 1 < NT) ? 0.f : NINF);
            rowmax[mi][0] = fmaxf(rowmax[mi][0], fmaxf(m0, m1));
            rowmax[mi][1] = fmaxf(rowmax[mi][1], fmaxf(m2, m3));
            colmax[ni][0] = fmaxf(colmax[ni][0],
                fmaxf(v0 ? cf[0] : NINF, v8 ? cf[2] : NINF));
            colmax[ni][1] = fmaxf(colmax[ni][1],
                fmaxf(v0 ? cf[1] : NINF, v8 ? cf[3] : NINF));
        }
    }

#pragma unroll
    for (int mi = 0; mi < 2; mi++)
#pragma unroll
        for (int h = 0; h < 2; h++) {
            float r = rowmax[mi][h];
            r = fmaxf(r, __shfl_xor_sync(0xffffffffu, r, 1));
            r = fmaxf(r, __shfl_xor_sync(0xffffffffu, r, 2));
            rowmax[mi][h] = r;
        }
    float rowsum = 0.f;
#pragma unroll
    for (int mi = 0; mi < 2; mi++) {
        const bool active = (mi == 0) || has2;
        int r0 = rb + mi * 16;
        if (active && r0 < NV)       rowsum += rowmax[mi][0];
        if (active && (r0 + 8) < NV) rowsum += rowmax[mi][1];
    }
    rowsum += __shfl_xor_sync(0xffffffffu, rowsum, 4);
    rowsum += __shfl_xor_sync(0xffffffffu, rowsum, 8);
    rowsum += __shfl_xor_sync(0xffffffffu, rowsum, 16);
    if (lane == 0) s_vsum[wid] = rowsum;

#pragma unroll
    for (int ni = 0; ni < 10; ni++)
#pragma unroll
        for (int h = 0; h < 2; h++) {
            float r = colmax[ni][h];
            r = fmaxf(r, __shfl_xor_sync(0xffffffffu, r, 4));
            r = fmaxf(r, __shfl_xor_sync(0xffffffffu, r, 8));
            r = fmaxf(r, __shfl_xor_sync(0xffffffffu, r, 16));
            colmax[ni][h] = r;
        }
    if (lane < 4) {
#pragma unroll
        for (int ni = 0; ni < 10; ni++) {
            int cc = ni * 8 + (lane << 1);
            s_colmax[wid][cc]     = colmax[ni][0];
            s_colmax[wid][cc + 1] = colmax[ni][1];
        }
    }
    __syncthreads();

    if (tid < 128) {
        float val = 0.f;
        if (tid < 80) {
            float cm = NINF;
#pragma unroll
            for (int w = 0; w < 8; w++) cm = fmaxf(cm, s_colmax[w][tid]);
            val = (tid < len) ? cm : 0.f;
        }
        s_tred[tid] = val;
    }
    __syncthreads();
#pragma unroll
    for (int s = 64; s > 0; s >>= 1) {
        if (tid < s) s_tred[tid] += s_tred[tid + s];
        __syncthreads();
    }
    if (tid == 0) {
        float vs = 0.f;
#pragma unroll
        for (int w = 0; w < 8; w++) vs += s_vsum[w];
        t2v[b * NQ + q] = s_tred[0] / (float)len;
        v2t[b * NQ + q] = vs / (float)NV;
    }
}

// ===========================================================================
extern "C" void kernel_launch(void* const* d_in, const int* in_sizes, int n_in,
                              void* d_out, int out_size)
{
    const float* visual_cls     = (const float*)d_in[0];
    const float* visual_tokens  = (const float*)d_in[1];
    const float* textual_cls    = (const float*)d_in[2];
    const float* textual_tokens = (const float*)d_in[3];
    const float* Wv_cls = (const float*)d_in[4];
    const float* bv_cls = (const float*)d_in[5];
    const float* Wt_cls = (const float*)d_in[6];
    const float* bt_cls = (const float*)d_in[7];
    const float* Wv_tok = (const float*)d_in[8];
    const float* bv_tok = (const float*)d_in[9];
    const float* Wt_tok = (const float*)d_in[10];
    const float* bt_tok = (const float*)d_in[11];
    const int*   text_length = (const int*)d_in[12];

    float* out = (float*)d_out;
    float* o_vcls = out;
    float* o_tcls = out + NB * NE;
    float* o_t2v  = out + 2 * NB * NE;
    float* o_v2t  = o_t2v + NB * NQ;

    {
        size_t n8 = CSEG3 / 8;
        int blocks = (int)((n8 + 255) / 256);
        convert_bf16<<<blocks, 256>>>(visual_tokens, textual_tokens, Wv_tok, Wt_tok);
    }

    proj_cls<<<dim3(2, 8, 2), 256>>>(visual_cls, Wv_cls, bv_cls, o_vcls,
                                     textual_cls, Wt_cls, bt_cls, o_tcls);

    cudaFuncSetAttribute(proj_mma2, cudaFuncAttributeMaxDynamicSharedMemorySize,
                         2 * PSTAGE);
    proj_mma2<<<dim3(VIS_BX, 4, 2), 256, 2 * PSTAGE>>>(bv_tok, bt_tok);

    l2norm_rows<<<(NB * NV + NQ * NT + 7) / 8, 256>>>();

    cudaFuncSetAttribute(stage2, cudaFuncAttributeMaxDynamicSharedMemorySize, SMEM_DYN);
    stage2<<<dim3(NQ, NB), 256, SMEM_DYN>>>(text_length, o_t2v, o_v2t);
}

// round 13
// speedup vs baseline: 4.7522x; 1.1369x over previous
#include <cuda_runtime.h>
#include <cuda_bf16.h>
#include <math.h>
#include <stdint.h>

// Problem dims (fixed)
#define NB 96
#define NQ 96
#define NV 197
#define NT 77
#define ND 768
#define NE 512

__device__ float         g_vtok_f32[(size_t)NB * NV * NE];
__device__ float         g_ttok_f32[(size_t)NQ * NT * NE];
__device__ __nv_bfloat16 g_vtok[(size_t)NB * NV * NE];
__device__ __nv_bfloat16 g_ttok[(size_t)NQ * NT * NE];
// bf16 pre-converted GEMM inputs
__device__ __nv_bfloat16 g_xvb[(size_t)NB * NV * ND];
__device__ __nv_bfloat16 g_xtb[(size_t)NQ * NT * ND];
__device__ __nv_bfloat16 g_wvb[(size_t)NE * ND];
__device__ __nv_bfloat16 g_wtb[(size_t)NE * ND];

__device__ __forceinline__ uint32_t smem_u32(const void* p) {
    uint32_t a;
    asm("{ .reg .u64 t; cvta.to.shared.u64 t, %1; cvt.u32.u64 %0, t; }"
        : "=r"(a) : "l"(p));
    return a;
}
__device__ __forceinline__ void ldmatrix_x4(uint32_t* r, uint32_t addr) {
    asm volatile("ldmatrix.sync.aligned.m8n8.x4.shared.b16 {%0,%1,%2,%3}, [%4];"
        : "=r"(r[0]), "=r"(r[1]), "=r"(r[2]), "=r"(r[3]) : "r"(addr));
}
__device__ __forceinline__ void mma_16816(float* c, const uint32_t* a, const uint32_t* b) {
    asm volatile("mma.sync.aligned.m16n8k16.row.col.f32.bf16.bf16.f32 "
        "{%0,%1,%2,%3}, {%4,%5,%6,%7}, {%8,%9}, {%0,%1,%2,%3};"
        : "+f"(c[0]), "+f"(c[1]), "+f"(c[2]), "+f"(c[3])
        : "r"(a[0]), "r"(a[1]), "r"(a[2]), "r"(a[3]), "r"(b[0]), "r"(b[1]));
}
__device__ __forceinline__ void cp16(uint32_t dst, const void* src, bool pred) {
    int sz = pred ? 16 : 0;
    asm volatile("cp.async.cg.shared.global [%0], [%1], 16, %2;"
        :: "r"(dst), "l"(src), "r"(sz) : "memory");
}
#define CP_COMMIT() asm volatile("cp.async.commit_group;" ::: "memory")
__device__ __forceinline__ uint4 f32x8_bf16(float4 a, float4 b) {
    uint4 r;
    __nv_bfloat162 p;
    p = __float22bfloat162_rn(make_float2(a.x, a.y)); r.x = *(uint32_t*)&p;
    p = __float22bfloat162_rn(make_float2(a.z, a.w)); r.y = *(uint32_t*)&p;
    p = __float22bfloat162_rn(make_float2(b.x, b.y)); r.z = *(uint32_t*)&p;
    p = __float22bfloat162_rn(make_float2(b.z, b.w)); r.w = *(uint32_t*)&p;
    return r;
}

// ===========================================================================
// Convert fp32 inputs -> bf16 operand buffers
// ===========================================================================
#define CSEG0 ((size_t)NB * NV * ND)
#define CSEG1 (CSEG0 + (size_t)NQ * NT * ND)
#define CSEG2 (CSEG1 + (size_t)NE * ND)
#define CSEG3 (CSEG2 + (size_t)NE * ND)

__global__ __launch_bounds__(256) void convert_bf16(
    const float* __restrict__ xv, const float* __restrict__ xt,
    const float* __restrict__ wv, const float* __restrict__ wt)
{
    size_t e = ((size_t)blockIdx.x * 256 + threadIdx.x) * 8;
    if (e >= CSEG3) return;
    const float* src;
    __nv_bfloat16* dst;
    size_t off;
    if (e < CSEG0)      { src = xv; dst = g_xvb; off = e; }
    else if (e < CSEG1) { src = xt; dst = g_xtb; off = e - CSEG0; }
    else if (e < CSEG2) { src = wv; dst = g_wvb; off = e - CSEG1; }
    else                { src = wt; dst = g_wtb; off = e - CSEG2; }
    const float4* p = (const float4*)(src + off);
    *(uint4*)(dst + off) = f32x8_bf16(p[0], p[1]);
}

// ===========================================================================
// cls projections (exact fp32 SIMT), one launch via blockIdx.z
// ===========================================================================
__global__ __launch_bounds__(256) void proj_cls(
    const float* __restrict__ Xv, const float* __restrict__ Wv,
    const float* __restrict__ bv, float* __restrict__ Yv,
    const float* __restrict__ Xt, const float* __restrict__ Wt,
    const float* __restrict__ bt, float* __restrict__ Yt)
{
    const float* X = blockIdx.z ? Xt : Xv;
    const float* W = blockIdx.z ? Wt : Wv;
    const float* bias = blockIdx.z ? bt : bv;
    float* Y = blockIdx.z ? Yt : Yv;
    const int R = NB;

    __shared__ float As[16][68];
    __shared__ float Bs[16][68];
    const int r0 = blockIdx.x * 64, e0 = blockIdx.y * 64;
    const int tid = threadIdx.x;
    const int ty = tid >> 4, tx = tid & 15;
    const int lrow = tid >> 2, lk4 = tid & 3;

    float acc[4][4];
#pragma unroll
    for (int i = 0; i < 4; i++)
#pragma unroll
        for (int j = 0; j < 4; j++) acc[i][j] = 0.f;

    const int r_ld = r0 + lrow;
    const float4 zero4 = make_float4(0.f, 0.f, 0.f, 0.f);

    for (int k0 = 0; k0 < ND; k0 += 16) {
        float4 av = (r_ld < R)
            ? *(const float4*)(X + (size_t)r_ld * ND + k0 + lk4 * 4) : zero4;
        float4 bv4 = *(const float4*)(W + (size_t)(e0 + lrow) * ND + k0 + lk4 * 4);
        __syncthreads();
        As[lk4 * 4 + 0][lrow] = av.x; As[lk4 * 4 + 1][lrow] = av.y;
        As[lk4 * 4 + 2][lrow] = av.z; As[lk4 * 4 + 3][lrow] = av.w;
        Bs[lk4 * 4 + 0][lrow] = bv4.x; Bs[lk4 * 4 + 1][lrow] = bv4.y;
        Bs[lk4 * 4 + 2][lrow] = bv4.z; Bs[lk4 * 4 + 3][lrow] = bv4.w;
        __syncthreads();
#pragma unroll
        for (int kk = 0; kk < 16; kk++) {
            float4 a = *(const float4*)&As[kk][ty * 4];
            float4 b = *(const float4*)&Bs[kk][tx * 4];
            float aa[4] = {a.x, a.y, a.z, a.w};
            float bb[4] = {b.x, b.y, b.z, b.w};
#pragma unroll
            for (int i = 0; i < 4; i++)
#pragma unroll
                for (int j = 0; j < 4; j++)
                    acc[i][j] = fmaf(aa[i], bb[j], acc[i][j]);
        }
    }
#pragma unroll
    for (int i = 0; i < 4; i++) {
        int r = r0 + ty * 4 + i;
        if (r < R) {
#pragma unroll
            for (int j = 0; j < 4; j++) {
                int e = e0 + tx * 4 + j;
                Y[(size_t)r * NE + e] = acc[i][j] + bias[e];
            }
        }
    }
}

// ===========================================================================
// Token projection v2 (unchanged)
// ===========================================================================
#define PPITCH 144
#define PBOFF  (128 * PPITCH)
#define PSTAGE (2 * PBOFF)
#define VIS_BX 148
#define TEX_BX 58

__global__ __launch_bounds__(256, 2) void proj_mma2(
    const float* __restrict__ bias_v, const float* __restrict__ bias_t)
{
    const int z = blockIdx.z;
    if (z == 1 && blockIdx.x >= TEX_BX) return;
    const int R = z ? (NQ * NT) : (NB * NV);
    const uint4* Xb = (const uint4*)(z ? g_xtb : g_xvb);
    const uint4* Wb = (const uint4*)(z ? g_wtb : g_wvb);
    const float* bias = z ? bias_t : bias_v;
    float* Y = z ? g_ttok_f32 : g_vtok_f32;

    extern __shared__ __align__(16) char psm[];
    const uint32_t st0 = smem_u32(psm), st1 = st0 + PSTAGE;

    const int tid = threadIdx.x, wid = tid >> 5, lane = tid & 31;
    const int r0 = blockIdx.x * 128, e0 = blockIdx.y * 128;
    const int mrow = (wid & 3) * 32, ncol = (wid >> 2) * 64;

    const uint32_t aoff = (uint32_t)(mrow + (lane & 7) + ((lane >> 3) & 1) * 8) * PPITCH
                        + (uint32_t)(lane >> 4) * 16;
    const uint32_t boff = PBOFF
                        + (uint32_t)(ncol + (lane & 7) + ((lane >> 4) << 3)) * PPITCH
                        + (uint32_t)((lane >> 3) & 1) * 16;

    float c[2][8][4];
#pragma unroll
    for (int mi = 0; mi < 2; mi++)
#pragma unroll
        for (int ni = 0; ni < 8; ni++)
#pragma unroll
            for (int j = 0; j < 4; j++) c[mi][ni][j] = 0.f;

    auto issue = [&](int ch, uint32_t sbase) {
        const int k4 = ch * 8;
#pragma unroll
        for (int it = 0; it < 8; it++) {
            int slot = it * 256 + tid, row = slot >> 3, seg = slot & 7;
            if (row < 128) {
                bool ok = (r0 + row) < R;
                const uint4* src = Xb + (ok ? (size_t)(r0 + row) * 96 : 0) + k4 + seg;
                cp16(sbase + (uint32_t)(row * PPITCH + seg * 16), src, ok);
            } else {
                int wr = row - 128;
                const uint4* src = Wb + (size_t)(e0 + wr) * 96 + k4 + seg;
                cp16(sbase + (uint32_t)(PBOFF + wr * PPITCH + seg * 16), src, true);
            }
        }
    };

    issue(0, st0); CP_COMMIT();
    issue(1, st1); CP_COMMIT();

    for (int ch = 0; ch < 12; ch++) {
        if (ch == 11) asm volatile("cp.async.wait_group 0;" ::: "memory");
        else          asm volatile("cp.async.wait_group 1;" ::: "memory");
        __syncthreads();

        const uint32_t sb = (ch & 1) ? st1 : st0;
        const uint32_t aa = sb + aoff, ba = sb + boff;
#pragma unroll
        for (int ks = 0; ks < 4; ks++) {
            uint32_t af[2][4], bf[16];
#pragma unroll
            for (int mi = 0; mi < 2; mi++)
                ldmatrix_x4(af[mi], aa + mi * (16 * PPITCH) + ks * 32);
#pragma unroll
            for (int nn = 0; nn < 4; nn++)
                ldmatrix_x4(bf + nn * 4, ba + nn * (16 * PPITCH) + ks * 32);
#pragma unroll
            for (int mi = 0; mi < 2; mi++)
#pragma unroll
                for (int ni = 0; ni < 8; ni++)
                    mma_16816(c[mi][ni], af[mi], bf + ni * 2);
        }
        __syncthreads();
        if (ch + 2 < 12) { issue(ch + 2, sb); CP_COMMIT(); }
    }

#pragma unroll
    for (int mi = 0; mi < 2; mi++) {
        int rr = r0 + mrow + mi * 16 + (lane >> 2);
        if (rr < R) {
#pragma unroll
            for (int ni = 0; ni < 8; ni++) {
                int e = e0 + ncol + ni * 8 + ((lane & 3) << 1);
                float2 o;
                o.x = c[mi][ni][0] + bias[e];
                o.y = c[mi][ni][1] + bias[e + 1];
                *(float2*)(Y + (size_t)rr * NE + e) = o;
                o.x = c[mi][ni][2] + bias[e];
                o.y = c[mi][ni][3] + bias[e + 1];
                *(float2*)(Y + (size_t)(rr + 8) * NE + e) = o;
            }
        }
    }
}

// ===========================================================================
// L2-normalize rows (fp32 in), write bf16 operand buffers
// ===========================================================================
__global__ __launch_bounds__(256) void l2norm_rows()
{
    const int NROWS_V = NB * NV;
    const int NROWS = NROWS_V + NQ * NT;
    int row = blockIdx.x * 8 + (threadIdx.x >> 5);
    int lane = threadIdx.x & 31;
    if (row >= NROWS) return;
    const float* src;
    __nv_bfloat16* dst;
    if (row < NROWS_V) {
        src = g_vtok_f32 + (size_t)row * NE;
        dst = g_vtok + (size_t)row * NE;
    } else {
        src = g_ttok_f32 + (size_t)(row - NROWS_V) * NE;
        dst = g_ttok + (size_t)(row - NROWS_V) * NE;
    }
    const float4* p4 = (const float4*)src;
    float s = 0.f;
#pragma unroll
    for (int i = lane; i < NE / 4; i += 32) {
        float4 v = p4[i];
        s += v.x * v.x + v.y * v.y + v.z * v.z + v.w * v.w;
    }
#pragma unroll
    for (int off = 16; off > 0; off >>= 1)
        s += __shfl_xor_sync(0xffffffffu, s, off);
    float inv = 1.f / fmaxf(sqrtf(s), 1e-12f);
    __nv_bfloat162* d2 = (__nv_bfloat162*)dst;
#pragma unroll
    for (int i = lane; i < NE / 4; i += 32) {
        float4 v = p4[i];
        d2[2 * i]     = __float22bfloat162_rn(make_float2(v.x * inv, v.y * inv));
        d2[2 * i + 1] = __float22bfloat162_rn(make_float2(v.z * inv, v.w * inv));
    }
}

// ===========================================================================
// Stage 2 v4: one CTA = (b, q); n-extent clamped to text_length[q].
//   nnlim = ceil(len/16) in [1,5]; columns >= nnlim*16 are never computed
//   (their logits are masked to 0 / unused in the reference).
//   M=208 asymmetric tiles; 256 thr, 2 CTAs/SM, 2-stage cp.async.
// ===========================================================================
#define APITCH 144
#define MROWS  208
#define BOFF2  (MROWS * APITCH)                // 29952
#define STAGE  (BOFF2 + 80 * APITCH)          // 41472
#define SMEM_DYN (2 * STAGE)                  // 82944 -> 2 CTAs/SM
#define NINF   (-INFINITY)

__global__ __launch_bounds__(256, 2) void stage2(
    const int* __restrict__ text_length,
    float* __restrict__ t2v, float* __restrict__ v2t)
{
    extern __shared__ __align__(16) char dsm[];
    __shared__ float s_colmax[8][84];
    __shared__ float s_vsum[8];
    __shared__ float s_tred[128];

    const int tid = threadIdx.x;
    const int wid = tid >> 5, lane = tid & 31;
    const int q = blockIdx.x, b = blockIdx.y;

    const int len = text_length[q];
    const int nnlim = (len + 15) >> 4;         // 1..5 active 16-col groups
    const int nrows = nnlim << 4;              // active B rows (rounded up)

    const uint4* Va = (const uint4*)(g_vtok + (size_t)b * NV * NE);
    const uint4* Tt = (const uint4*)(g_ttok + (size_t)q * NT * NE);

    const uint32_t st0 = smem_u32(dsm), st1 = st0 + STAGE;

    // asymmetric m-tile assignment (warp-uniform)
    const int mcnt = (wid < 5) ? 2 : 1;
    const int moff = (wid < 5) ? wid * 32 : 160 + (wid - 5) * 16;
    const bool has2 = (mcnt == 2);

    const uint32_t aoff = (uint32_t)(moff + (lane & 7) + ((lane >> 3) & 1) * 8) * APITCH
                        + (uint32_t)(lane >> 4) * 16;
    const uint32_t boff = BOFF2
                        + (uint32_t)((lane & 7) + ((lane >> 4) << 3)) * APITCH
                        + (uint32_t)((lane >> 3) & 1) * 16;

    float c[2][10][4];
#pragma unroll
    for (int mi = 0; mi < 2; mi++)
#pragma unroll
        for (int ni = 0; ni < 10; ni++)
#pragma unroll
            for (int j = 0; j < 4; j++) c[mi][ni][j] = 0.f;

    auto issue = [&](int ch, uint32_t sbase) {
        const int k4 = ch * 8;
#pragma unroll
        for (int it = 0; it < 7; it++) {           // A: 208 rows x 8 = 1664 slots
            int slot = it * 256 + tid;
            if (slot < MROWS * 8) {
                int row = slot >> 3, seg = slot & 7;
                bool ok = row < NV;
                const uint4* src = Va + (ok ? row * 64 : 0) + k4 + seg;
                cp16(sbase + (uint32_t)(row * APITCH + seg * 16), src, ok);
            }
        }
#pragma unroll
        for (int it = 0; it < 3; it++) {           // B: only active rows
            int slot = it * 256 + tid;
            if (slot < 640) {
                int row = slot >> 3, seg = slot & 7;
                if (row < nrows) {
                    bool ok = row < NT;
                    const uint4* src = Tt + (ok ? row * 64 : 0) + k4 + seg;
                    cp16(sbase + (uint32_t)(BOFF2 + row * APITCH + seg * 16), src, ok);
                }
            }
        }
    };

    issue(0, st0); CP_COMMIT();
    issue(1, st1); CP_COMMIT();

    for (int ch = 0; ch < 8; ch++) {
        if (ch == 7) asm volatile("cp.async.wait_group 0;" ::: "memory");
        else         asm volatile("cp.async.wait_group 1;" ::: "memory");
        __syncthreads();

        const uint32_t sb = (ch & 1) ? st1 : st0;
        const uint32_t aa = sb + aoff, ba = sb + boff;
#pragma unroll
        for (int ks = 0; ks < 4; ks++) {
            uint32_t af[2][4], bf[20];
            ldmatrix_x4(af[0], aa + ks * 32);
            if (has2) ldmatrix_x4(af[1], aa + 16 * APITCH + ks * 32);
#pragma unroll
            for (int nn = 0; nn < 5; nn++)
                if (nn < nnlim)
                    ldmatrix_x4(bf + nn * 4, ba + nn * (16 * APITCH) + ks * 32);
#pragma unroll
            for (int ni = 0; ni < 10; ni++)
                if (ni < 2 * nnlim)
                    mma_16816(c[0][ni], af[0], bf + ni * 2);
            if (has2) {
#pragma unroll
                for (int ni = 0; ni < 10; ni++)
                    if (ni < 2 * nnlim)
                        mma_16816(c[1][ni], af[1], bf + ni * 2);
            }
        }
        __syncthreads();
        if (ch + 2 < 8) { issue(ch + 2, sb); CP_COMMIT(); }
    }

    // ---- register/shfl epilogue (static indexing, 'active' predicates) ----
    // For tl >= len the masked value (0 or -inf) is used, never cf -> skipped
    // columns (cf still 0-init) are never observed.
    const int rb = moff + (lane >> 2);

    float rowmax[2][2] = {{NINF, NINF}, {NINF, NINF}};
    float colmax[10][2];
#pragma unroll
    for (int ni = 0; ni < 10; ni++) { colmax[ni][0] = NINF; colmax[ni][1] = NINF; }

#pragma unroll
    for (int mi = 0; mi < 2; mi++) {
        const bool active = (mi == 0) || has2;
        int r0 = rb + mi * 16;
        bool v0 = active && (r0 < NV), v8 = active && ((r0 + 8) < NV);
#pragma unroll
        for (int ni = 0; ni < 10; ni++) {
            int tl = ni * 8 + ((lane & 3) << 1);
            float* cf = c[mi][ni];
            float m0 = (tl     < len) ? cf[0] : ((tl     < NT) ? 0.f : NINF);
            float m1 = (tl + 1 < len) ? cf[1] : ((tl + 1 < NT) ? 0.f : NINF);
            float m2 = (tl     < len) ? cf[2] : ((tl     < NT) ? 0.f : NINF);
            float m3 = (tl + 1 < len) ? cf[3] : ((tl + 1 < NT) ? 0.f : NINF);
            rowmax[mi][0] = fmaxf(rowmax[mi][0], fmaxf(m0, m1));
            rowmax[mi][1] = fmaxf(rowmax[mi][1], fmaxf(m2, m3));
            colmax[ni][0] = fmaxf(colmax[ni][0],
                fmaxf(v0 ? cf[0] : NINF, v8 ? cf[2] : NINF));
            colmax[ni][1] = fmaxf(colmax[ni][1],
                fmaxf(v0 ? cf[1] : NINF, v8 ? cf[3] : NINF));
        }
    }

#pragma unroll
    for (int mi = 0; mi < 2; mi++)
#pragma unroll
        for (int h = 0; h < 2; h++) {
            float r = rowmax[mi][h];
            r = fmaxf(r, __shfl_xor_sync(0xffffffffu, r, 1));
            r = fmaxf(r, __shfl_xor_sync(0xffffffffu, r, 2));
            rowmax[mi][h] = r;
        }
    float rowsum = 0.f;
#pragma unroll
    for (int mi = 0; mi < 2; mi++) {
        const bool active = (mi == 0) || has2;
        int r0 = rb + mi * 16;
        if (active && r0 < NV)       rowsum += rowmax[mi][0];
        if (active && (r0 + 8) < NV) rowsum += rowmax[mi][1];
    }
    rowsum += __shfl_xor_sync(0xffffffffu, rowsum, 4);
    rowsum += __shfl_xor_sync(0xffffffffu, rowsum, 8);
    rowsum += __shfl_xor_sync(0xffffffffu, rowsum, 16);
    if (lane == 0) s_vsum[wid] = rowsum;

#pragma unroll
    for (int ni = 0; ni < 10; ni++)
#pragma unroll
        for (int h = 0; h < 2; h++) {
            float r = colmax[ni][h];
            r = fmaxf(r, __shfl_xor_sync(0xffffffffu, r, 4));
            r = fmaxf(r, __shfl_xor_sync(0xffffffffu, r, 8));
            r = fmaxf(r, __shfl_xor_sync(0xffffffffu, r, 16));
            colmax[ni][h] = r;
        }
    if (lane < 4) {
#pragma unroll
        for (int ni = 0; ni < 10; ni++) {
            int cc = ni * 8 + (lane << 1);
            s_colmax[wid][cc]     = colmax[ni][0];
            s_colmax[wid][cc + 1] = colmax[ni][1];
        }
    }
    __syncthreads();

    if (tid < 128) {
        float val = 0.f;
        if (tid < 80) {
            float cm = NINF;
#pragma unroll
            for (int w = 0; w < 8; w++) cm = fmaxf(cm, s_colmax[w][tid]);
            val = (tid < len) ? cm : 0.f;
        }
        s_tred[tid] = val;
    }
    __syncthreads();
#pragma unroll
    for (int s = 64; s > 0; s >>= 1) {
        if (tid < s) s_tred[tid] += s_tred[tid + s];
        __syncthreads();
    }
    if (tid == 0) {
        float vs = 0.f;
#pragma unroll
        for (int w = 0; w < 8; w++) vs += s_vsum[w];
        t2v[b * NQ + q] = s_tred[0] / (float)len;
        v2t[b * NQ + q] = vs / (float)NV;
    }
}

// ===========================================================================
extern "C" void kernel_launch(void* const* d_in, const int* in_sizes, int n_in,
                              void* d_out, int out_size)
{
    const float* visual_cls     = (const float*)d_in[0];
    const float* visual_tokens  = (const float*)d_in[1];
    const float* textual_cls    = (const float*)d_in[2];
    const float* textual_tokens = (const float*)d_in[3];
    const float* Wv_cls = (const float*)d_in[4];
    const float* bv_cls = (const float*)d_in[5];
    const float* Wt_cls = (const float*)d_in[6];
    const float* bt_cls = (const float*)d_in[7];
    const float* Wv_tok = (const float*)d_in[8];
    const float* bv_tok = (const float*)d_in[9];
    const float* Wt_tok = (const float*)d_in[10];
    const float* bt_tok = (const float*)d_in[11];
    const int*   text_length = (const int*)d_in[12];

    float* out = (float*)d_out;
    float* o_vcls = out;
    float* o_tcls = out + NB * NE;
    float* o_t2v  = out + 2 * NB * NE;
    float* o_v2t  = o_t2v + NB * NQ;

    {
        size_t n8 = CSEG3 / 8;
        int blocks = (int)((n8 + 255) / 256);
        convert_bf16<<<blocks, 256>>>(visual_tokens, textual_tokens, Wv_tok, Wt_tok);
    }

    proj_cls<<<dim3(2, 8, 2), 256>>>(visual_cls, Wv_cls, bv_cls, o_vcls,
                                     textual_cls, Wt_cls, bt_cls, o_tcls);

    cudaFuncSetAttribute(proj_mma2, cudaFuncAttributeMaxDynamicSharedMemorySize,
                         2 * PSTAGE);
    proj_mma2<<<dim3(VIS_BX, 4, 2), 256, 2 * PSTAGE>>>(bv_tok, bt_tok);

    l2norm_rows<<<(NB * NV + NQ * NT + 7) / 8, 256>>>();

    cudaFuncSetAttribute(stage2, cudaFuncAttributeMaxDynamicSharedMemorySize, SMEM_DYN);
    stage2<<<dim3(NQ, NB), 256, SMEM_DYN>>>(text_length, o_t2v, o_v2t);
}

// round 14
// speedup vs baseline: 5.0864x; 1.0703x over previous
#include <cuda_runtime.h>
#include <cuda_bf16.h>
#include <math.h>
#include <stdint.h>

// Problem dims (fixed)
#define NB 96
#define NQ 96
#define NV 197
#define NT 77
#define ND 768
#define NE 512

__device__ float         g_vtok_f32[(size_t)NB * NV * NE];
__device__ float         g_ttok_f32[(size_t)NQ * NT * NE];
__device__ __nv_bfloat16 g_vtok[(size_t)NB * NV * NE];
__device__ __nv_bfloat16 g_ttok[(size_t)NQ * NT * NE];
// bf16 pre-converted GEMM inputs
__device__ __nv_bfloat16 g_xvb[(size_t)NB * NV * ND];
__device__ __nv_bfloat16 g_xtb[(size_t)NQ * NT * ND];
__device__ __nv_bfloat16 g_wvb[(size_t)NE * ND];
__device__ __nv_bfloat16 g_wtb[(size_t)NE * ND];

__device__ __forceinline__ uint32_t smem_u32(const void* p) {
    uint32_t a;
    asm("{ .reg .u64 t; cvta.to.shared.u64 t, %1; cvt.u32.u64 %0, t; }"
        : "=r"(a) : "l"(p));
    return a;
}
__device__ __forceinline__ void ldmatrix_x4(uint32_t* r, uint32_t addr) {
    asm volatile("ldmatrix.sync.aligned.m8n8.x4.shared.b16 {%0,%1,%2,%3}, [%4];"
        : "=r"(r[0]), "=r"(r[1]), "=r"(r[2]), "=r"(r[3]) : "r"(addr));
}
__device__ __forceinline__ void mma_16816(float* c, const uint32_t* a, const uint32_t* b) {
    asm volatile("mma.sync.aligned.m16n8k16.row.col.f32.bf16.bf16.f32 "
        "{%0,%1,%2,%3}, {%4,%5,%6,%7}, {%8,%9}, {%0,%1,%2,%3};"
        : "+f"(c[0]), "+f"(c[1]), "+f"(c[2]), "+f"(c[3])
        : "r"(a[0]), "r"(a[1]), "r"(a[2]), "r"(a[3]), "r"(b[0]), "r"(b[1]));
}
__device__ __forceinline__ void cp16(uint32_t dst, const void* src, bool pred) {
    int sz = pred ? 16 : 0;
    asm volatile("cp.async.cg.shared.global [%0], [%1], 16, %2;"
        :: "r"(dst), "l"(src), "r"(sz) : "memory");
}
#define CP_COMMIT() asm volatile("cp.async.commit_group;" ::: "memory")
__device__ __forceinline__ uint4 f32x8_bf16(float4 a, float4 b) {
    uint4 r;
    __nv_bfloat162 p;
    p = __float22bfloat162_rn(make_float2(a.x, a.y)); r.x = *(uint32_t*)&p;
    p = __float22bfloat162_rn(make_float2(a.z, a.w)); r.y = *(uint32_t*)&p;
    p = __float22bfloat162_rn(make_float2(b.x, b.y)); r.z = *(uint32_t*)&p;
    p = __float22bfloat162_rn(make_float2(b.z, b.w)); r.w = *(uint32_t*)&p;
    return r;
}

// ===========================================================================
// Convert fp32 inputs -> bf16 operand buffers
// ===========================================================================
#define CSEG0 ((size_t)NB * NV * ND)
#define CSEG1 (CSEG0 + (size_t)NQ * NT * ND)
#define CSEG2 (CSEG1 + (size_t)NE * ND)
#define CSEG3 (CSEG2 + (size_t)NE * ND)

__global__ __launch_bounds__(256) void convert_bf16(
    const float* __restrict__ xv, const float* __restrict__ xt,
    const float* __restrict__ wv, const float* __restrict__ wt)
{
    size_t e = ((size_t)blockIdx.x * 256 + threadIdx.x) * 8;
    if (e >= CSEG3) return;
    const float* src;
    __nv_bfloat16* dst;
    size_t off;
    if (e < CSEG0)      { src = xv; dst = g_xvb; off = e; }
    else if (e < CSEG1) { src = xt; dst = g_xtb; off = e - CSEG0; }
    else if (e < CSEG2) { src = wv; dst = g_wvb; off = e - CSEG1; }
    else                { src = wt; dst = g_wtb; off = e - CSEG2; }
    const float4* p = (const float4*)(src + off);
    *(uint4*)(dst + off) = f32x8_bf16(p[0], p[1]);
}

// ===========================================================================
// cls projections (exact fp32 SIMT), one launch via blockIdx.z
// ===========================================================================
__global__ __launch_bounds__(256) void proj_cls(
    const float* __restrict__ Xv, const float* __restrict__ Wv,
    const float* __restrict__ bv, float* __restrict__ Yv,
    const float* __restrict__ Xt, const float* __restrict__ Wt,
    const float* __restrict__ bt, float* __restrict__ Yt)
{
    const float* X = blockIdx.z ? Xt : Xv;
    const float* W = blockIdx.z ? Wt : Wv;
    const float* bias = blockIdx.z ? bt : bv;
    float* Y = blockIdx.z ? Yt : Yv;
    const int R = NB;

    __shared__ float As[16][68];
    __shared__ float Bs[16][68];
    const int r0 = blockIdx.x * 64, e0 = blockIdx.y * 64;
    const int tid = threadIdx.x;
    const int ty = tid >> 4, tx = tid & 15;
    const int lrow = tid >> 2, lk4 = tid & 3;

    float acc[4][4];
#pragma unroll
    for (int i = 0; i < 4; i++)
#pragma unroll
        for (int j = 0; j < 4; j++) acc[i][j] = 0.f;

    const int r_ld = r0 + lrow;
    const float4 zero4 = make_float4(0.f, 0.f, 0.f, 0.f);

    for (int k0 = 0; k0 < ND; k0 += 16) {
        float4 av = (r_ld < R)
            ? *(const float4*)(X + (size_t)r_ld * ND + k0 + lk4 * 4) : zero4;
        float4 bv4 = *(const float4*)(W + (size_t)(e0 + lrow) * ND + k0 + lk4 * 4);
        __syncthreads();
        As[lk4 * 4 + 0][lrow] = av.x; As[lk4 * 4 + 1][lrow] = av.y;
        As[lk4 * 4 + 2][lrow] = av.z; As[lk4 * 4 + 3][lrow] = av.w;
        Bs[lk4 * 4 + 0][lrow] = bv4.x; Bs[lk4 * 4 + 1][lrow] = bv4.y;
        Bs[lk4 * 4 + 2][lrow] = bv4.z; Bs[lk4 * 4 + 3][lrow] = bv4.w;
        __syncthreads();
#pragma unroll
        for (int kk = 0; kk < 16; kk++) {
            float4 a = *(const float4*)&As[kk][ty * 4];
            float4 b = *(const float4*)&Bs[kk][tx * 4];
            float aa[4] = {a.x, a.y, a.z, a.w};
            float bb[4] = {b.x, b.y, b.z, b.w};
#pragma unroll
            for (int i = 0; i < 4; i++)
#pragma unroll
                for (int j = 0; j < 4; j++)
                    acc[i][j] = fmaf(aa[i], bb[j], acc[i][j]);
        }
    }
#pragma unroll
    for (int i = 0; i < 4; i++) {
        int r = r0 + ty * 4 + i;
        if (r < R) {
#pragma unroll
            for (int j = 0; j < 4; j++) {
                int e = e0 + tx * 4 + j;
                Y[(size_t)r * NE + e] = acc[i][j] + bias[e];
            }
        }
    }
}

// ===========================================================================
// Token projection v2 (unchanged)
// ===========================================================================
#define PPITCH 144
#define PBOFF  (128 * PPITCH)
#define PSTAGE (2 * PBOFF)
#define VIS_BX 148
#define TEX_BX 58

__global__ __launch_bounds__(256, 2) void proj_mma2(
    const float* __restrict__ bias_v, const float* __restrict__ bias_t)
{
    const int z = blockIdx.z;
    if (z == 1 && blockIdx.x >= TEX_BX) return;
    const int R = z ? (NQ * NT) : (NB * NV);
    const uint4* Xb = (const uint4*)(z ? g_xtb : g_xvb);
    const uint4* Wb = (const uint4*)(z ? g_wtb : g_wvb);
    const float* bias = z ? bias_t : bias_v;
    float* Y = z ? g_ttok_f32 : g_vtok_f32;

    extern __shared__ __align__(16) char psm[];
    const uint32_t st0 = smem_u32(psm), st1 = st0 + PSTAGE;

    const int tid = threadIdx.x, wid = tid >> 5, lane = tid & 31;
    const int r0 = blockIdx.x * 128, e0 = blockIdx.y * 128;
    const int mrow = (wid & 3) * 32, ncol = (wid >> 2) * 64;

    const uint32_t aoff = (uint32_t)(mrow + (lane & 7) + ((lane >> 3) & 1) * 8) * PPITCH
                        + (uint32_t)(lane >> 4) * 16;
    const uint32_t boff = PBOFF
                        + (uint32_t)(ncol + (lane & 7) + ((lane >> 4) << 3)) * PPITCH
                        + (uint32_t)((lane >> 3) & 1) * 16;

    float c[2][8][4];
#pragma unroll
    for (int mi = 0; mi < 2; mi++)
#pragma unroll
        for (int ni = 0; ni < 8; ni++)
#pragma unroll
            for (int j = 0; j < 4; j++) c[mi][ni][j] = 0.f;

    auto issue = [&](int ch, uint32_t sbase) {
        const int k4 = ch * 8;
#pragma unroll
        for (int it = 0; it < 8; it++) {
            int slot = it * 256 + tid, row = slot >> 3, seg = slot & 7;
            if (row < 128) {
                bool ok = (r0 + row) < R;
                const uint4* src = Xb + (ok ? (size_t)(r0 + row) * 96 : 0) + k4 + seg;
                cp16(sbase + (uint32_t)(row * PPITCH + seg * 16), src, ok);
            } else {
                int wr = row - 128;
                const uint4* src = Wb + (size_t)(e0 + wr) * 96 + k4 + seg;
                cp16(sbase + (uint32_t)(PBOFF + wr * PPITCH + seg * 16), src, true);
            }
        }
    };

    issue(0, st0); CP_COMMIT();
    issue(1, st1); CP_COMMIT();

    for (int ch = 0; ch < 12; ch++) {
        if (ch == 11) asm volatile("cp.async.wait_group 0;" ::: "memory");
        else          asm volatile("cp.async.wait_group 1;" ::: "memory");
        __syncthreads();

        const uint32_t sb = (ch & 1) ? st1 : st0;
        const uint32_t aa = sb + aoff, ba = sb + boff;
#pragma unroll
        for (int ks = 0; ks < 4; ks++) {
            uint32_t af[2][4], bf[16];
#pragma unroll
            for (int mi = 0; mi < 2; mi++)
                ldmatrix_x4(af[mi], aa + mi * (16 * PPITCH) + ks * 32);
#pragma unroll
            for (int nn = 0; nn < 4; nn++)
                ldmatrix_x4(bf + nn * 4, ba + nn * (16 * PPITCH) + ks * 32);
#pragma unroll
            for (int mi = 0; mi < 2; mi++)
#pragma unroll
                for (int ni = 0; ni < 8; ni++)
                    mma_16816(c[mi][ni], af[mi], bf + ni * 2);
        }
        __syncthreads();
        if (ch + 2 < 12) { issue(ch + 2, sb); CP_COMMIT(); }
    }

#pragma unroll
    for (int mi = 0; mi < 2; mi++) {
        int rr = r0 + mrow + mi * 16 + (lane >> 2);
        if (rr < R) {
#pragma unroll
            for (int ni = 0; ni < 8; ni++) {
                int e = e0 + ncol + ni * 8 + ((lane & 3) << 1);
                float2 o;
                o.x = c[mi][ni][0] + bias[e];
                o.y = c[mi][ni][1] + bias[e + 1];
                *(float2*)(Y + (size_t)rr * NE + e) = o;
                o.x = c[mi][ni][2] + bias[e];
                o.y = c[mi][ni][3] + bias[e + 1];
                *(float2*)(Y + (size_t)(rr + 8) * NE + e) = o;
            }
        }
    }
}

// ===========================================================================
// L2-normalize rows (fp32 in), write bf16 operand buffers
// ===========================================================================
__global__ __launch_bounds__(256) void l2norm_rows()
{
    const int NROWS_V = NB * NV;
    const int NROWS = NROWS_V + NQ * NT;
    int row = blockIdx.x * 8 + (threadIdx.x >> 5);
    int lane = threadIdx.x & 31;
    if (row >= NROWS) return;
    const float* src;
    __nv_bfloat16* dst;
    if (row < NROWS_V) {
        src = g_vtok_f32 + (size_t)row * NE;
        dst = g_vtok + (size_t)row * NE;
    } else {
        src = g_ttok_f32 + (size_t)(row - NROWS_V) * NE;
        dst = g_ttok + (size_t)(row - NROWS_V) * NE;
    }
    const float4* p4 = (const float4*)src;
    float s = 0.f;
#pragma unroll
    for (int i = lane; i < NE / 4; i += 32) {
        float4 v = p4[i];
        s += v.x * v.x + v.y * v.y + v.z * v.z + v.w * v.w;
    }
#pragma unroll
    for (int off = 16; off > 0; off >>= 1)
        s += __shfl_xor_sync(0xffffffffu, s, off);
    float inv = 1.f / fmaxf(sqrtf(s), 1e-12f);
    __nv_bfloat162* d2 = (__nv_bfloat162*)dst;
#pragma unroll
    for (int i = lane; i < NE / 4; i += 32) {
        float4 v = p4[i];
        d2[2 * i]     = __float22bfloat162_rn(make_float2(v.x * inv, v.y * inv));
        d2[2 * i + 1] = __float22bfloat162_rn(make_float2(v.z * inv, v.w * inv));
    }
}

// ===========================================================================
// Stage 2 v4 (unchanged from R13): one CTA = (b, q); n-extent length-clamped.
// ===========================================================================
#define APITCH 144
#define MROWS  208
#define BOFF2  (MROWS * APITCH)
#define STAGE  (BOFF2 + 80 * APITCH)
#define SMEM_DYN (2 * STAGE)
#define NINF   (-INFINITY)

__global__ __launch_bounds__(256, 2) void stage2(
    const int* __restrict__ text_length,
    float* __restrict__ t2v, float* __restrict__ v2t)
{
    extern __shared__ __align__(16) char dsm[];
    __shared__ float s_colmax[8][84];
    __shared__ float s_vsum[8];
    __shared__ float s_tred[128];

    const int tid = threadIdx.x;
    const int wid = tid >> 5, lane = tid & 31;
    const int q = blockIdx.x, b = blockIdx.y;

    const int len = text_length[q];
    const int nnlim = (len + 15) >> 4;
    const int nrows = nnlim << 4;

    const uint4* Va = (const uint4*)(g_vtok + (size_t)b * NV * NE);
    const uint4* Tt = (const uint4*)(g_ttok + (size_t)q * NT * NE);

    const uint32_t st0 = smem_u32(dsm), st1 = st0 + STAGE;

    const int mcnt = (wid < 5) ? 2 : 1;
    const int moff = (wid < 5) ? wid * 32 : 160 + (wid - 5) * 16;
    const bool has2 = (mcnt == 2);

    const uint32_t aoff = (uint32_t)(moff + (lane & 7) + ((lane >> 3) & 1) * 8) * APITCH
                        + (uint32_t)(lane >> 4) * 16;
    const uint32_t boff = BOFF2
                        + (uint32_t)((lane & 7) + ((lane >> 4) << 3)) * APITCH
                        + (uint32_t)((lane >> 3) & 1) * 16;

    float c[2][10][4];
#pragma unroll
    for (int mi = 0; mi < 2; mi++)
#pragma unroll
        for (int ni = 0; ni < 10; ni++)
#pragma unroll
            for (int j = 0; j < 4; j++) c[mi][ni][j] = 0.f;

    auto issue = [&](int ch, uint32_t sbase) {
        const int k4 = ch * 8;
#pragma unroll
        for (int it = 0; it < 7; it++) {
            int slot = it * 256 + tid;
            if (slot < MROWS * 8) {
                int row = slot >> 3, seg = slot & 7;
                bool ok = row < NV;
                const uint4* src = Va + (ok ? row * 64 : 0) + k4 + seg;
                cp16(sbase + (uint32_t)(row * APITCH + seg * 16), src, ok);
            }
        }
#pragma unroll
        for (int it = 0; it < 3; it++) {
            int slot = it * 256 + tid;
            if (slot < 640) {
                int row = slot >> 3, seg = slot & 7;
                if (row < nrows) {
                    bool ok = row < NT;
                    const uint4* src = Tt + (ok ? row * 64 : 0) + k4 + seg;
                    cp16(sbase + (uint32_t)(BOFF2 + row * APITCH + seg * 16), src, ok);
                }
            }
        }
    };

    issue(0, st0); CP_COMMIT();
    issue(1, st1); CP_COMMIT();

    for (int ch = 0; ch < 8; ch++) {
        if (ch == 7) asm volatile("cp.async.wait_group 0;" ::: "memory");
        else         asm volatile("cp.async.wait_group 1;" ::: "memory");
        __syncthreads();

        const uint32_t sb = (ch & 1) ? st1 : st0;
        const uint32_t aa = sb + aoff, ba = sb + boff;
#pragma unroll
        for (int ks = 0; ks < 4; ks++) {
            uint32_t af[2][4], bf[20];
            ldmatrix_x4(af[0], aa + ks * 32);
            if (has2) ldmatrix_x4(af[1], aa + 16 * APITCH + ks * 32);
#pragma unroll
            for (int nn = 0; nn < 5; nn++)
                if (nn < nnlim)
                    ldmatrix_x4(bf + nn * 4, ba + nn * (16 * APITCH) + ks * 32);
#pragma unroll
            for (int ni = 0; ni < 10; ni++)
                if (ni < 2 * nnlim)
                    mma_16816(c[0][ni], af[0], bf + ni * 2);
            if (has2) {
#pragma unroll
                for (int ni = 0; ni < 10; ni++)
                    if (ni < 2 * nnlim)
                        mma_16816(c[1][ni], af[1], bf + ni * 2);
            }
        }
        __syncthreads();
        if (ch + 2 < 8) { issue(ch + 2, sb); CP_COMMIT(); }
    }

    // ---- register/shfl epilogue ----
    const int rb = moff + (lane >> 2);

    float rowmax[2][2] = {{NINF, NINF}, {NINF, NINF}};
    float colmax[10][2];
#pragma unroll
    for (int ni = 0; ni < 10; ni++) { colmax[ni][0] = NINF; colmax[ni][1] = NINF; }

#pragma unroll
    for (int mi = 0; mi < 2; mi++) {
        const bool active = (mi == 0) || has2;
        int r0 = rb + mi * 16;
        bool v0 = active && (r0 < NV), v8 = active && ((r0 + 8) < NV);
#pragma unroll
        for (int ni = 0; ni < 10; ni++) {
            int tl = ni * 8 + ((lane & 3) << 1);
            float* cf = c[mi][ni];
            float m0 = (tl     < len) ? cf[0] : ((tl     < NT) ? 0.f : NINF);
            float m1 = (tl + 1 < len) ? cf[1] : ((tl + 1 < NT) ? 0.f : NINF);
            float m2 = (tl     < len) ? cf[2] : ((tl     < NT) ? 0.f : NINF);
            float m3 = (tl + 1 < len) ? cf[3] : ((tl + 1 < NT) ? 0.f : NINF);
            rowmax[mi][0] = fmaxf(rowmax[mi][0], fmaxf(m0, m1));
            rowmax[mi][1] = fmaxf(rowmax[mi][1], fmaxf(m2, m3));
            colmax[ni][0] = fmaxf(colmax[ni][0],
                fmaxf(v0 ? cf[0] : NINF, v8 ? cf[2] : NINF));
            colmax[ni][1] = fmaxf(colmax[ni][1],
                fmaxf(v0 ? cf[1] : NINF, v8 ? cf[3] : NINF));
        }
    }

#pragma unroll
    for (int mi = 0; mi < 2; mi++)
#pragma unroll
        for (int h = 0; h < 2; h++) {
            float r = rowmax[mi][h];
            r = fmaxf(r, __shfl_xor_sync(0xffffffffu, r, 1));
            r = fmaxf(r, __shfl_xor_sync(0xffffffffu, r, 2));
            rowmax[mi][h] = r;
        }
    float rowsum = 0.f;
#pragma unroll
    for (int mi = 0; mi < 2; mi++) {
        const bool active = (mi == 0) || has2;
        int r0 = rb + mi * 16;
        if (active && r0 < NV)       rowsum += rowmax[mi][0];
        if (active && (r0 + 8) < NV) rowsum += rowmax[mi][1];
    }
    rowsum += __shfl_xor_sync(0xffffffffu, rowsum, 4);
    rowsum += __shfl_xor_sync(0xffffffffu, rowsum, 8);
    rowsum += __shfl_xor_sync(0xffffffffu, rowsum, 16);
    if (lane == 0) s_vsum[wid] = rowsum;

#pragma unroll
    for (int ni = 0; ni < 10; ni++)
#pragma unroll
        for (int h = 0; h < 2; h++) {
            float r = colmax[ni][h];
            r = fmaxf(r, __shfl_xor_sync(0xffffffffu, r, 4));
            r = fmaxf(r, __shfl_xor_sync(0xffffffffu, r, 8));
            r = fmaxf(r, __shfl_xor_sync(0xffffffffu, r, 16));
            colmax[ni][h] = r;
        }
    if (lane < 4) {
#pragma unroll
        for (int ni = 0; ni < 10; ni++) {
            int cc = ni * 8 + (lane << 1);
            s_colmax[wid][cc]     = colmax[ni][0];
            s_colmax[wid][cc + 1] = colmax[ni][1];
        }
    }
    __syncthreads();

    if (tid < 128) {
        float val = 0.f;
        if (tid < 80) {
            float cm = NINF;
#pragma unroll
            for (int w = 0; w < 8; w++) cm = fmaxf(cm, s_colmax[w][tid]);
            val = (tid < len) ? cm : 0.f;
        }
        s_tred[tid] = val;
    }
    __syncthreads();
#pragma unroll
    for (int s = 64; s > 0; s >>= 1) {
        if (tid < s) s_tred[tid] += s_tred[tid + s];
        __syncthreads();
    }
    if (tid == 0) {
        float vs = 0.f;
#pragma unroll
        for (int w = 0; w < 8; w++) vs += s_vsum[w];
        t2v[b * NQ + q] = s_tred[0] / (float)len;
        v2t[b * NQ + q] = vs / (float)NV;
    }
}

// ===========================================================================
extern "C" void kernel_launch(void* const* d_in, const int* in_sizes, int n_in,
                              void* d_out, int out_size)
{
    const float* visual_cls     = (const float*)d_in[0];
    const float* visual_tokens  = (const float*)d_in[1];
    const float* textual_cls    = (const float*)d_in[2];
    const float* textual_tokens = (const float*)d_in[3];
    const float* Wv_cls = (const float*)d_in[4];
    const float* bv_cls = (const float*)d_in[5];
    const float* Wt_cls = (const float*)d_in[6];
    const float* bt_cls = (const float*)d_in[7];
    const float* Wv_tok = (const float*)d_in[8];
    const float* bv_tok = (const float*)d_in[9];
    const float* Wt_tok = (const float*)d_in[10];
    const float* bt_tok = (const float*)d_in[11];
    const int*   text_length = (const int*)d_in[12];

    float* out = (float*)d_out;
    float* o_vcls = out;
    float* o_tcls = out + NB * NE;
    float* o_t2v  = out + 2 * NB * NE;
    float* o_v2t  = o_t2v + NB * NQ;

    // One-time side-stream + events (host resources, not device memory)
    static cudaStream_t s2 = nullptr;
    static cudaEvent_t ev_fork = nullptr, ev_join = nullptr;
    if (s2 == nullptr) {
        cudaStreamCreateWithFlags(&s2, cudaStreamNonBlocking);
        cudaEventCreateWithFlags(&ev_fork, cudaEventDisableTiming);
        cudaEventCreateWithFlags(&ev_join, cudaEventDisableTiming);
    }

    // Fork: proj_cls is independent of the token chain -> side stream,
    // overlapping convert_bf16 (HBM-bound) and proj_mma2 (low issue%).
    cudaEventRecord(ev_fork, 0);
    cudaStreamWaitEvent(s2, ev_fork, 0);
    proj_cls<<<dim3(2, 8, 2), 256, 0, s2>>>(visual_cls, Wv_cls, bv_cls, o_vcls,
                                            textual_cls, Wt_cls, bt_cls, o_tcls);
    cudaEventRecord(ev_join, s2);

    // Main chain
    {
        size_t n8 = CSEG3 / 8;
        int blocks = (int)((n8 + 255) / 256);
        convert_bf16<<<blocks, 256>>>(visual_tokens, textual_tokens, Wv_tok, Wt_tok);
    }

    cudaFuncSetAttribute(proj_mma2, cudaFuncAttributeMaxDynamicSharedMemorySize,
                         2 * PSTAGE);
    proj_mma2<<<dim3(VIS_BX, 4, 2), 256, 2 * PSTAGE>>>(bv_tok, bt_tok);

    l2norm_rows<<<(NB * NV + NQ * NT + 7) / 8, 256>>>();

    cudaFuncSetAttribute(stage2, cudaFuncAttributeMaxDynamicSharedMemorySize, SMEM_DYN);
    stage2<<<dim3(NQ, NB), 256, SMEM_DYN>>>(text_length, o_t2v, o_v2t);

    // Join side stream back into the capture/main stream
    cudaStreamWaitEvent(0, ev_join, 0);
}

// round 15
// speedup vs baseline: 5.2402x; 1.0302x over previous
#include <cuda_runtime.h>
#include <cuda_bf16.h>
#include <math.h>
#include <stdint.h>

// Problem dims (fixed)
#define NB 96
#define NQ 96
#define NV 197
#define NT 77
#define ND 768
#define NE 512

__device__ float         g_vtok_f32[(size_t)NB * NV * NE];
__device__ float         g_ttok_f32[(size_t)NQ * NT * NE];
__device__ __nv_bfloat16 g_vtok[(size_t)NB * NV * NE];
__device__ __nv_bfloat16 g_ttok[(size_t)NQ * NT * NE];
// bf16 pre-converted GEMM inputs
__device__ __nv_bfloat16 g_xvb[(size_t)NB * NV * ND];
__device__ __nv_bfloat16 g_xtb[(size_t)NQ * NT * ND];
__device__ __nv_bfloat16 g_wvb[(size_t)NE * ND];
__device__ __nv_bfloat16 g_wtb[(size_t)NE * ND];

__device__ __forceinline__ uint32_t smem_u32(const void* p) {
    uint32_t a;
    asm("{ .reg .u64 t; cvta.to.shared.u64 t, %1; cvt.u32.u64 %0, t; }"
        : "=r"(a) : "l"(p));
    return a;
}
__device__ __forceinline__ void ldmatrix_x4(uint32_t* r, uint32_t addr) {
    asm volatile("ldmatrix.sync.aligned.m8n8.x4.shared.b16 {%0,%1,%2,%3}, [%4];"
        : "=r"(r[0]), "=r"(r[1]), "=r"(r[2]), "=r"(r[3]) : "r"(addr));
}
__device__ __forceinline__ void mma_16816(float* c, const uint32_t* a, const uint32_t* b) {
    asm volatile("mma.sync.aligned.m16n8k16.row.col.f32.bf16.bf16.f32 "
        "{%0,%1,%2,%3}, {%4,%5,%6,%7}, {%8,%9}, {%0,%1,%2,%3};"
        : "+f"(c[0]), "+f"(c[1]), "+f"(c[2]), "+f"(c[3])
        : "r"(a[0]), "r"(a[1]), "r"(a[2]), "r"(a[3]), "r"(b[0]), "r"(b[1]));
}
__device__ __forceinline__ void cp16(uint32_t dst, const void* src, bool pred) {
    int sz = pred ? 16 : 0;
    asm volatile("cp.async.cg.shared.global [%0], [%1], 16, %2;"
        :: "r"(dst), "l"(src), "r"(sz) : "memory");
}
#define CP_COMMIT() asm volatile("cp.async.commit_group;" ::: "memory")
__device__ __forceinline__ uint4 f32x8_bf16(float4 a, float4 b) {
    uint4 r;
    __nv_bfloat162 p;
    p = __float22bfloat162_rn(make_float2(a.x, a.y)); r.x = *(uint32_t*)&p;
    p = __float22bfloat162_rn(make_float2(a.z, a.w)); r.y = *(uint32_t*)&p;
    p = __float22bfloat162_rn(make_float2(b.x, b.y)); r.z = *(uint32_t*)&p;
    p = __float22bfloat162_rn(make_float2(b.z, b.w)); r.w = *(uint32_t*)&p;
    return r;
}

// ===========================================================================
// Convert fp32 inputs -> bf16 operand buffers
// ===========================================================================
#define CSEG0 ((size_t)NB * NV * ND)
#define CSEG1 (CSEG0 + (size_t)NQ * NT * ND)
#define CSEG2 (CSEG1 + (size_t)NE * ND)
#define CSEG3 (CSEG2 + (size_t)NE * ND)

__global__ __launch_bounds__(256) void convert_bf16(
    const float* __restrict__ xv, const float* __restrict__ xt,
    const float* __restrict__ wv, const float* __restrict__ wt)
{
    size_t e = ((size_t)blockIdx.x * 256 + threadIdx.x) * 8;
    if (e >= CSEG3) return;
    const float* src;
    __nv_bfloat16* dst;
    size_t off;
    if (e < CSEG0)      { src = xv; dst = g_xvb; off = e; }
    else if (e < CSEG1) { src = xt; dst = g_xtb; off = e - CSEG0; }
    else if (e < CSEG2) { src = wv; dst = g_wvb; off = e - CSEG1; }
    else                { src = wt; dst = g_wtb; off = e - CSEG2; }
    const float4* p = (const float4*)(src + off);
    *(uint4*)(dst + off) = f32x8_bf16(p[0], p[1]);
}

// ===========================================================================
// cls projections (exact fp32 SIMT), one launch via blockIdx.z
// ===========================================================================
__global__ __launch_bounds__(256) void proj_cls(
    const float* __restrict__ Xv, const float* __restrict__ Wv,
    const float* __restrict__ bv, float* __restrict__ Yv,
    const float* __restrict__ Xt, const float* __restrict__ Wt,
    const float* __restrict__ bt, float* __restrict__ Yt)
{
    const float* X = blockIdx.z ? Xt : Xv;
    const float* W = blockIdx.z ? Wt : Wv;
    const float* bias = blockIdx.z ? bt : bv;
    float* Y = blockIdx.z ? Yt : Yv;
    const int R = NB;

    __shared__ float As[16][68];
    __shared__ float Bs[16][68];
    const int r0 = blockIdx.x * 64, e0 = blockIdx.y * 64;
    const int tid = threadIdx.x;
    const int ty = tid >> 4, tx = tid & 15;
    const int lrow = tid >> 2, lk4 = tid & 3;

    float acc[4][4];
#pragma unroll
    for (int i = 0; i < 4; i++)
#pragma unroll
        for (int j = 0; j < 4; j++) acc[i][j] = 0.f;

    const int r_ld = r0 + lrow;
    const float4 zero4 = make_float4(0.f, 0.f, 0.f, 0.f);

    for (int k0 = 0; k0 < ND; k0 += 16) {
        float4 av = (r_ld < R)
            ? *(const float4*)(X + (size_t)r_ld * ND + k0 + lk4 * 4) : zero4;
        float4 bv4 = *(const float4*)(W + (size_t)(e0 + lrow) * ND + k0 + lk4 * 4);
        __syncthreads();
        As[lk4 * 4 + 0][lrow] = av.x; As[lk4 * 4 + 1][lrow] = av.y;
        As[lk4 * 4 + 2][lrow] = av.z; As[lk4 * 4 + 3][lrow] = av.w;
        Bs[lk4 * 4 + 0][lrow] = bv4.x; Bs[lk4 * 4 + 1][lrow] = bv4.y;
        Bs[lk4 * 4 + 2][lrow] = bv4.z; Bs[lk4 * 4 + 3][lrow] = bv4.w;
        __syncthreads();
#pragma unroll
        for (int kk = 0; kk < 16; kk++) {
            float4 a = *(const float4*)&As[kk][ty * 4];
            float4 b = *(const float4*)&Bs[kk][tx * 4];
            float aa[4] = {a.x, a.y, a.z, a.w};
            float bb[4] = {b.x, b.y, b.z, b.w};
#pragma unroll
            for (int i = 0; i < 4; i++)
#pragma unroll
                for (int j = 0; j < 4; j++)
                    acc[i][j] = fmaf(aa[i], bb[j], acc[i][j]);
        }
    }
#pragma unroll
    for (int i = 0; i < 4; i++) {
        int r = r0 + ty * 4 + i;
        if (r < R) {
#pragma unroll
            for (int j = 0; j < 4; j++) {
                int e = e0 + tx * 4 + j;
                Y[(size_t)r * NE + e] = acc[i][j] + bias[e];
            }
        }
    }
}

// ===========================================================================
// Token projection v2 (unchanged)
// ===========================================================================
#define PPITCH 144
#define PBOFF  (128 * PPITCH)
#define PSTAGE (2 * PBOFF)
#define VIS_BX 148
#define TEX_BX 58

__global__ __launch_bounds__(256, 2) void proj_mma2(
    const float* __restrict__ bias_v, const float* __restrict__ bias_t)
{
    const int z = blockIdx.z;
    if (z == 1 && blockIdx.x >= TEX_BX) return;
    const int R = z ? (NQ * NT) : (NB * NV);
    const uint4* Xb = (const uint4*)(z ? g_xtb : g_xvb);
    const uint4* Wb = (const uint4*)(z ? g_wtb : g_wvb);
    const float* bias = z ? bias_t : bias_v;
    float* Y = z ? g_ttok_f32 : g_vtok_f32;

    extern __shared__ __align__(16) char psm[];
    const uint32_t st0 = smem_u32(psm), st1 = st0 + PSTAGE;

    const int tid = threadIdx.x, wid = tid >> 5, lane = tid & 31;
    const int r0 = blockIdx.x * 128, e0 = blockIdx.y * 128;
    const int mrow = (wid & 3) * 32, ncol = (wid >> 2) * 64;

    const uint32_t aoff = (uint32_t)(mrow + (lane & 7) + ((lane >> 3) & 1) * 8) * PPITCH
                        + (uint32_t)(lane >> 4) * 16;
    const uint32_t boff = PBOFF
                        + (uint32_t)(ncol + (lane & 7) + ((lane >> 4) << 3)) * PPITCH
                        + (uint32_t)((lane >> 3) & 1) * 16;

    float c[2][8][4];
#pragma unroll
    for (int mi = 0; mi < 2; mi++)
#pragma unroll
        for (int ni = 0; ni < 8; ni++)
#pragma unroll
            for (int j = 0; j < 4; j++) c[mi][ni][j] = 0.f;

    auto issue = [&](int ch, uint32_t sbase) {
        const int k4 = ch * 8;
#pragma unroll
        for (int it = 0; it < 8; it++) {
            int slot = it * 256 + tid, row = slot >> 3, seg = slot & 7;
            if (row < 128) {
                bool ok = (r0 + row) < R;
                const uint4* src = Xb + (ok ? (size_t)(r0 + row) * 96 : 0) + k4 + seg;
                cp16(sbase + (uint32_t)(row * PPITCH + seg * 16), src, ok);
            } else {
                int wr = row - 128;
                const uint4* src = Wb + (size_t)(e0 + wr) * 96 + k4 + seg;
                cp16(sbase + (uint32_t)(PBOFF + wr * PPITCH + seg * 16), src, true);
            }
        }
    };

    issue(0, st0); CP_COMMIT();
    issue(1, st1); CP_COMMIT();

    for (int ch = 0; ch < 12; ch++) {
        if (ch == 11) asm volatile("cp.async.wait_group 0;" ::: "memory");
        else          asm volatile("cp.async.wait_group 1;" ::: "memory");
        __syncthreads();

        const uint32_t sb = (ch & 1) ? st1 : st0;
        const uint32_t aa = sb + aoff, ba = sb + boff;
#pragma unroll
        for (int ks = 0; ks < 4; ks++) {
            uint32_t af[2][4], bf[16];
#pragma unroll
            for (int mi = 0; mi < 2; mi++)
                ldmatrix_x4(af[mi], aa + mi * (16 * PPITCH) + ks * 32);
#pragma unroll
            for (int nn = 0; nn < 4; nn++)
                ldmatrix_x4(bf + nn * 4, ba + nn * (16 * PPITCH) + ks * 32);
#pragma unroll
            for (int mi = 0; mi < 2; mi++)
#pragma unroll
                for (int ni = 0; ni < 8; ni++)
                    mma_16816(c[mi][ni], af[mi], bf + ni * 2);
        }
        __syncthreads();
        if (ch + 2 < 12) { issue(ch + 2, sb); CP_COMMIT(); }
    }

#pragma unroll
    for (int mi = 0; mi < 2; mi++) {
        int rr = r0 + mrow + mi * 16 + (lane >> 2);
        if (rr < R) {
#pragma unroll
            for (int ni = 0; ni < 8; ni++) {
                int e = e0 + ncol + ni * 8 + ((lane & 3) << 1);
                float2 o;
                o.x = c[mi][ni][0] + bias[e];
                o.y = c[mi][ni][1] + bias[e + 1];
                *(float2*)(Y + (size_t)rr * NE + e) = o;
                o.x = c[mi][ni][2] + bias[e];
                o.y = c[mi][ni][3] + bias[e + 1];
                *(float2*)(Y + (size_t)(rr + 8) * NE + e) = o;
            }
        }
    }
}

// ===========================================================================
// L2-normalize rows (fp32 in), write bf16 operand buffers
// ===========================================================================
__global__ __launch_bounds__(256) void l2norm_rows()
{
    const int NROWS_V = NB * NV;
    const int NROWS = NROWS_V + NQ * NT;
    int row = blockIdx.x * 8 + (threadIdx.x >> 5);
    int lane = threadIdx.x & 31;
    if (row >= NROWS) return;
    const float* src;
    __nv_bfloat16* dst;
    if (row < NROWS_V) {
        src = g_vtok_f32 + (size_t)row * NE;
        dst = g_vtok + (size_t)row * NE;
    } else {
        src = g_ttok_f32 + (size_t)(row - NROWS_V) * NE;
        dst = g_ttok + (size_t)(row - NROWS_V) * NE;
    }
    const float4* p4 = (const float4*)src;
    float s = 0.f;
#pragma unroll
    for (int i = lane; i < NE / 4; i += 32) {
        float4 v = p4[i];
        s += v.x * v.x + v.y * v.y + v.z * v.z + v.w * v.w;
    }
#pragma unroll
    for (int off = 16; off > 0; off >>= 1)
        s += __shfl_xor_sync(0xffffffffu, s, off);
    float inv = 1.f / fmaxf(sqrtf(s), 1e-12f);
    __nv_bfloat162* d2 = (__nv_bfloat162*)dst;
#pragma unroll
    for (int i = lane; i < NE / 4; i += 32) {
        float4 v = p4[i];
        d2[2 * i]     = __float22bfloat162_rn(make_float2(v.x * inv, v.y * inv));
        d2[2 * i + 1] = __float22bfloat162_rn(make_float2(v.z * inv, v.w * inv));
    }
}

// ===========================================================================
// Stage 2 v5: one sync per chunk (wait -> sync -> issue-next -> MMA),
//   slim shuffle epilogue, dead cp slots skipped. Math identical to v4.
// ===========================================================================
#define APITCH 144
#define MROWS  208
#define BOFF2  (MROWS * APITCH)
#define STAGE  (BOFF2 + 80 * APITCH)
#define SMEM_DYN (2 * STAGE)
#define NINF   (-INFINITY)

__global__ __launch_bounds__(256, 2) void stage2(
    const int* __restrict__ text_length,
    float* __restrict__ t2v, float* __restrict__ v2t)
{
    extern __shared__ __align__(16) char dsm[];
    __shared__ float s_colmax[8][84];
    __shared__ float s_vsum[8];
    __shared__ float s_part[8];

    const int tid = threadIdx.x;
    const int wid = tid >> 5, lane = tid & 31;
    const int q = blockIdx.x, b = blockIdx.y;

    const int len = text_length[q];
    const int nnlim = (len + 15) >> 4;
    const int nrows = nnlim << 4;

    const uint4* Va = (const uint4*)(g_vtok + (size_t)b * NV * NE);
    const uint4* Tt = (const uint4*)(g_ttok + (size_t)q * NT * NE);

    const uint32_t st0 = smem_u32(dsm), st1 = st0 + STAGE;

    const int mcnt = (wid < 5) ? 2 : 1;
    const int moff = (wid < 5) ? wid * 32 : 160 + (wid - 5) * 16;
    const bool has2 = (mcnt == 2);

    const uint32_t aoff = (uint32_t)(moff + (lane & 7) + ((lane >> 3) & 1) * 8) * APITCH
                        + (uint32_t)(lane >> 4) * 16;
    const uint32_t boff = BOFF2
                        + (uint32_t)((lane & 7) + ((lane >> 4) << 3)) * APITCH
                        + (uint32_t)((lane >> 3) & 1) * 16;

    float c[2][10][4];
#pragma unroll
    for (int mi = 0; mi < 2; mi++)
#pragma unroll
        for (int ni = 0; ni < 10; ni++)
#pragma unroll
            for (int j = 0; j < 4; j++) c[mi][ni][j] = 0.f;

    // A real rows only (pad rows 197-207 skipped; garbage c there is masked)
    auto issue = [&](int ch, uint32_t sbase) {
        const int k4 = ch * 8;
#pragma unroll
        for (int it = 0; it < 7; it++) {           // A: 197 rows x 8 = 1576 slots
            int slot = it * 256 + tid;
            if (slot < NV * 8) {
                int row = slot >> 3, seg = slot & 7;
                cp16(sbase + (uint32_t)(row * APITCH + seg * 16),
                     Va + row * 64 + k4 + seg, true);
            }
        }
#pragma unroll
        for (int it = 0; it < 3; it++) {           // B: active rows only
            int slot = it * 256 + tid;
            if (slot < 640) {
                int row = slot >> 3, seg = slot & 7;
                if (row < nrows) {
                    bool ok = row < NT;
                    const uint4* src = Tt + (ok ? row * 64 : 0) + k4 + seg;
                    cp16(sbase + (uint32_t)(BOFF2 + row * APITCH + seg * 16), src, ok);
                }
            }
        }
    };

    issue(0, st0); CP_COMMIT();

    for (int ch = 0; ch < 8; ch++) {
        asm volatile("cp.async.wait_group 0;" ::: "memory");
        __syncthreads();   // chunk ch visible to all; prev chunk's buffer drained

        const uint32_t sb = (ch & 1) ? st1 : st0;
        if (ch + 1 < 8) {                     // refill the other buffer
            issue(ch + 1, (ch & 1) ? st0 : st1);
            CP_COMMIT();
        }

        const uint32_t aa = sb + aoff, ba = sb + boff;
#pragma unroll
        for (int ks = 0; ks < 4; ks++) {
            uint32_t af[2][4], bf[20];
            ldmatrix_x4(af[0], aa + ks * 32);
            if (has2) ldmatrix_x4(af[1], aa + 16 * APITCH + ks * 32);
#pragma unroll
            for (int nn = 0; nn < 5; nn++)
                if (nn < nnlim)
                    ldmatrix_x4(bf + nn * 4, ba + nn * (16 * APITCH) + ks * 32);
#pragma unroll
            for (int ni = 0; ni < 10; ni++)
                if (ni < 2 * nnlim)
                    mma_16816(c[0][ni], af[0], bf + ni * 2);
            if (has2) {
#pragma unroll
                for (int ni = 0; ni < 10; ni++)
                    if (ni < 2 * nnlim)
                        mma_16816(c[1][ni], af[1], bf + ni * 2);
            }
        }
    }

    // ---- register/shfl epilogue ----
    const int rb = moff + (lane >> 2);

    float rowmax[2][2] = {{NINF, NINF}, {NINF, NINF}};
    float colmax[10][2];
#pragma unroll
    for (int ni = 0; ni < 10; ni++) { colmax[ni][0] = NINF; colmax[ni][1] = NINF; }

#pragma unroll
    for (int mi = 0; mi < 2; mi++) {
        const bool active = (mi == 0) || has2;
        int r0 = rb + mi * 16;
        bool v0 = active && (r0 < NV), v8 = active && ((r0 + 8) < NV);
#pragma unroll
        for (int ni = 0; ni < 10; ni++) {
            int tl = ni * 8 + ((lane & 3) << 1);
            float* cf = c[mi][ni];
            float m0 = (tl     < len) ? cf[0] : ((tl     < NT) ? 0.f : NINF);
            float m1 = (tl + 1 < len) ? cf[1] : ((tl + 1 < NT) ? 0.f : NINF);
            float m2 = (tl     < len) ? cf[2] : ((tl     < NT) ? 0.f : NINF);
            float m3 = (tl + 1 < len) ? cf[3] : ((tl + 1 < NT) ? 0.f : NINF);
            rowmax[mi][0] = fmaxf(rowmax[mi][0], fmaxf(m0, m1));
            rowmax[mi][1] = fmaxf(rowmax[mi][1], fmaxf(m2, m3));
            colmax[ni][0] = fmaxf(colmax[ni][0],
                fmaxf(v0 ? cf[0] : NINF, v8 ? cf[2] : NINF));
            colmax[ni][1] = fmaxf(colmax[ni][1],
                fmaxf(v0 ? cf[1] : NINF, v8 ? cf[3] : NINF));
        }
    }

#pragma unroll
    for (int mi = 0; mi < 2; mi++)
#pragma unroll
        for (int h = 0; h < 2; h++) {
            float r = rowmax[mi][h];
            r = fmaxf(r, __shfl_xor_sync(0xffffffffu, r, 1));
            r = fmaxf(r, __shfl_xor_sync(0xffffffffu, r, 2));
            rowmax[mi][h] = r;
        }
    float rowsum = 0.f;
#pragma unroll
    for (int mi = 0; mi < 2; mi++) {
        const bool active = (mi == 0) || has2;
        int r0 = rb + mi * 16;
        if (active && r0 < NV)       rowsum += rowmax[mi][0];
        if (active && (r0 + 8) < NV) rowsum += rowmax[mi][1];
    }
    rowsum += __shfl_xor_sync(0xffffffffu, rowsum, 4);
    rowsum += __shfl_xor_sync(0xffffffffu, rowsum, 8);
    rowsum += __shfl_xor_sync(0xffffffffu, rowsum, 16);
    if (lane == 0) s_vsum[wid] = rowsum;

#pragma unroll
    for (int ni = 0; ni < 10; ni++)
#pragma unroll
        for (int h = 0; h < 2; h++) {
            float r = colmax[ni][h];
            r = fmaxf(r, __shfl_xor_sync(0xffffffffu, r, 4));
            r = fmaxf(r, __shfl_xor_sync(0xffffffffu, r, 8));
            r = fmaxf(r, __shfl_xor_sync(0xffffffffu, r, 16));
            colmax[ni][h] = r;
        }
    if (lane < 4) {
#pragma unroll
        for (int ni = 0; ni < 10; ni++) {
            int cc = ni * 8 + (lane << 1);
            s_colmax[wid][cc]     = colmax[ni][0];
            s_colmax[wid][cc + 1] = colmax[ni][1];
        }
    }
    __syncthreads();

    // t2v sum via warp shuffles (replaces 7-sync tree)
    float val = 0.f;
    if (tid < 80) {
        float cm = NINF;
#pragma unroll
        for (int w = 0; w < 8; w++) cm = fmaxf(cm, s_colmax[w][tid]);
        val = (tid < len) ? cm : 0.f;
    }
#pragma unroll
    for (int off = 16; off > 0; off >>= 1)
        val += __shfl_xor_sync(0xffffffffu, val, off);
    if (lane == 0) s_part[wid] = val;
    __syncthreads();

    if (tid == 0) {
        float ts = s_part[0] + s_part[1] + s_part[2] + s_part[3];   // warps 4-7 hold 0
        float vs = 0.f;
#pragma unroll
        for (int w = 0; w < 8; w++) vs += s_vsum[w];
        t2v[b * NQ + q] = ts / (float)len;
        v2t[b * NQ + q] = vs / (float)NV;
    }
}

// ===========================================================================
extern "C" void kernel_launch(void* const* d_in, const int* in_sizes, int n_in,
                              void* d_out, int out_size)
{
    const float* visual_cls     = (const float*)d_in[0];
    const float* visual_tokens  = (const float*)d_in[1];
    const float* textual_cls    = (const float*)d_in[2];
    const float* textual_tokens = (const float*)d_in[3];
    const float* Wv_cls = (const float*)d_in[4];
    const float* bv_cls = (const float*)d_in[5];
    const float* Wt_cls = (const float*)d_in[6];
    const float* bt_cls = (const float*)d_in[7];
    const float* Wv_tok = (const float*)d_in[8];
    const float* bv_tok = (const float*)d_in[9];
    const float* Wt_tok = (const float*)d_in[10];
    const float* bt_tok = (const float*)d_in[11];
    const int*   text_length = (const int*)d_in[12];

    float* out = (float*)d_out;
    float* o_vcls = out;
    float* o_tcls = out + NB * NE;
    float* o_t2v  = out + 2 * NB * NE;
    float* o_v2t  = o_t2v + NB * NQ;

    static cudaStream_t s2 = nullptr;
    static cudaEvent_t ev_fork = nullptr, ev_join = nullptr;
    if (s2 == nullptr) {
        cudaStreamCreateWithFlags(&s2, cudaStreamNonBlocking);
        cudaEventCreateWithFlags(&ev_fork, cudaEventDisableTiming);
        cudaEventCreateWithFlags(&ev_join, cudaEventDisableTiming);
    }

    // Fork: independent cls projections on side stream
    cudaEventRecord(ev_fork, 0);
    cudaStreamWaitEvent(s2, ev_fork, 0);
    proj_cls<<<dim3(2, 8, 2), 256, 0, s2>>>(visual_cls, Wv_cls, bv_cls, o_vcls,
                                            textual_cls, Wt_cls, bt_cls, o_tcls);
    cudaEventRecord(ev_join, s2);

    // Main chain
    {
        size_t n8 = CSEG3 / 8;
        int blocks = (int)((n8 + 255) / 256);
        convert_bf16<<<blocks, 256>>>(visual_tokens, textual_tokens, Wv_tok, Wt_tok);
    }

    cudaFuncSetAttribute(proj_mma2, cudaFuncAttributeMaxDynamicSharedMemorySize,
                         2 * PSTAGE);
    proj_mma2<<<dim3(VIS_BX, 4, 2), 256, 2 * PSTAGE>>>(bv_tok, bt_tok);

    l2norm_rows<<<(NB * NV + NQ * NT + 7) / 8, 256>>>();

    cudaFuncSetAttribute(stage2, cudaFuncAttributeMaxDynamicSharedMemorySize, SMEM_DYN);
    stage2<<<dim3(NQ, NB), 256, SMEM_DYN>>>(text_length, o_t2v, o_v2t);

    cudaStreamWaitEvent(0, ev_join, 0);
}

// round 16
// speedup vs baseline: 5.6908x; 1.0860x over previous
#include <cuda_runtime.h>
#include <cuda_bf16.h>
#include <math.h>
#include <stdint.h>

// Problem dims (fixed)
#define NB 96
#define NQ 96
#define NV 197
#define NT 77
#define ND 768
#define NE 512

__device__ float         g_vtok_f32[(size_t)NB * NV * NE];
__device__ float         g_ttok_f32[(size_t)NQ * NT * NE];
__device__ __nv_bfloat16 g_vtok[(size_t)NB * NV * NE];
__device__ __nv_bfloat16 g_ttok[(size_t)NQ * NT * NE];
// bf16 pre-converted GEMM inputs
__device__ __nv_bfloat16 g_xvb[(size_t)NB * NV * ND];
__device__ __nv_bfloat16 g_xtb[(size_t)NQ * NT * ND];
__device__ __nv_bfloat16 g_wvb[(size_t)NE * ND];
__device__ __nv_bfloat16 g_wtb[(size_t)NE * ND];

__device__ __forceinline__ uint32_t smem_u32(const void* p) {
    uint32_t a;
    asm("{ .reg .u64 t; cvta.to.shared.u64 t, %1; cvt.u32.u64 %0, t; }"
        : "=r"(a) : "l"(p));
    return a;
}
__device__ __forceinline__ void ldmatrix_x4(uint32_t* r, uint32_t addr) {
    asm volatile("ldmatrix.sync.aligned.m8n8.x4.shared.b16 {%0,%1,%2,%3}, [%4];"
        : "=r"(r[0]), "=r"(r[1]), "=r"(r[2]), "=r"(r[3]) : "r"(addr));
}
__device__ __forceinline__ void mma_16816(float* c, const uint32_t* a, const uint32_t* b) {
    asm volatile("mma.sync.aligned.m16n8k16.row.col.f32.bf16.bf16.f32 "
        "{%0,%1,%2,%3}, {%4,%5,%6,%7}, {%8,%9}, {%0,%1,%2,%3};"
        : "+f"(c[0]), "+f"(c[1]), "+f"(c[2]), "+f"(c[3])
        : "r"(a[0]), "r"(a[1]), "r"(a[2]), "r"(a[3]), "r"(b[0]), "r"(b[1]));
}
__device__ __forceinline__ void cp16(uint32_t dst, const void* src, bool pred) {
    int sz = pred ? 16 : 0;
    asm volatile("cp.async.cg.shared.global [%0], [%1], 16, %2;"
        :: "r"(dst), "l"(src), "r"(sz) : "memory");
}
#define CP_COMMIT() asm volatile("cp.async.commit_group;" ::: "memory")
__device__ __forceinline__ uint4 f32x8_bf16(float4 a, float4 b) {
    uint4 r;
    __nv_bfloat162 p;
    p = __float22bfloat162_rn(make_float2(a.x, a.y)); r.x = *(uint32_t*)&p;
    p = __float22bfloat162_rn(make_float2(a.z, a.w)); r.y = *(uint32_t*)&p;
    p = __float22bfloat162_rn(make_float2(b.x, b.y)); r.z = *(uint32_t*)&p;
    p = __float22bfloat162_rn(make_float2(b.z, b.w)); r.w = *(uint32_t*)&p;
    return r;
}

// ===========================================================================
// Convert fp32 inputs -> bf16 operand buffers
// ===========================================================================
#define CSEG0 ((size_t)NB * NV * ND)
#define CSEG1 (CSEG0 + (size_t)NQ * NT * ND)
#define CSEG2 (CSEG1 + (size_t)NE * ND)
#define CSEG3 (CSEG2 + (size_t)NE * ND)

__global__ __launch_bounds__(256) void convert_bf16(
    const float* __restrict__ xv, const float* __restrict__ xt,
    const float* __restrict__ wv, const float* __restrict__ wt)
{
    size_t e = ((size_t)blockIdx.x * 256 + threadIdx.x) * 8;
    if (e >= CSEG3) return;
    const float* src;
    __nv_bfloat16* dst;
    size_t off;
    if (e < CSEG0)      { src = xv; dst = g_xvb; off = e; }
    else if (e < CSEG1) { src = xt; dst = g_xtb; off = e - CSEG0; }
    else if (e < CSEG2) { src = wv; dst = g_wvb; off = e - CSEG1; }
    else                { src = wt; dst = g_wtb; off = e - CSEG2; }
    const float4* p = (const float4*)(src + off);
    *(uint4*)(dst + off) = f32x8_bf16(p[0], p[1]);
}

// ===========================================================================
// cls projections (exact fp32 SIMT), one launch via blockIdx.z
// ===========================================================================
__global__ __launch_bounds__(256) void proj_cls(
    const float* __restrict__ Xv, const float* __restrict__ Wv,
    const float* __restrict__ bv, float* __restrict__ Yv,
    const float* __restrict__ Xt, const float* __restrict__ Wt,
    const float* __restrict__ bt, float* __restrict__ Yt)
{
    const float* X = blockIdx.z ? Xt : Xv;
    const float* W = blockIdx.z ? Wt : Wv;
    const float* bias = blockIdx.z ? bt : bv;
    float* Y = blockIdx.z ? Yt : Yv;
    const int R = NB;

    __shared__ float As[16][68];
    __shared__ float Bs[16][68];
    const int r0 = blockIdx.x * 64, e0 = blockIdx.y * 64;
    const int tid = threadIdx.x;
    const int ty = tid >> 4, tx = tid & 15;
    const int lrow = tid >> 2, lk4 = tid & 3;

    float acc[4][4];
#pragma unroll
    for (int i = 0; i < 4; i++)
#pragma unroll
        for (int j = 0; j < 4; j++) acc[i][j] = 0.f;

    const int r_ld = r0 + lrow;
    const float4 zero4 = make_float4(0.f, 0.f, 0.f, 0.f);

    for (int k0 = 0; k0 < ND; k0 += 16) {
        float4 av = (r_ld < R)
            ? *(const float4*)(X + (size_t)r_ld * ND + k0 + lk4 * 4) : zero4;
        float4 bv4 = *(const float4*)(W + (size_t)(e0 + lrow) * ND + k0 + lk4 * 4);
        __syncthreads();
        As[lk4 * 4 + 0][lrow] = av.x; As[lk4 * 4 + 1][lrow] = av.y;
        As[lk4 * 4 + 2][lrow] = av.z; As[lk4 * 4 + 3][lrow] = av.w;
        Bs[lk4 * 4 + 0][lrow] = bv4.x; Bs[lk4 * 4 + 1][lrow] = bv4.y;
        Bs[lk4 * 4 + 2][lrow] = bv4.z; Bs[lk4 * 4 + 3][lrow] = bv4.w;
        __syncthreads();
#pragma unroll
        for (int kk = 0; kk < 16; kk++) {
            float4 a = *(const float4*)&As[kk][ty * 4];
            float4 b = *(const float4*)&Bs[kk][tx * 4];
            float aa[4] = {a.x, a.y, a.z, a.w};
            float bb[4] = {b.x, b.y, b.z, b.w};
#pragma unroll
            for (int i = 0; i < 4; i++)
#pragma unroll
                for (int j = 0; j < 4; j++)
                    acc[i][j] = fmaf(aa[i], bb[j], acc[i][j]);
        }
    }
#pragma unroll
    for (int i = 0; i < 4; i++) {
        int r = r0 + ty * 4 + i;
        if (r < R) {
#pragma unroll
            for (int j = 0; j < 4; j++) {
                int e = e0 + tx * 4 + j;
                Y[(size_t)r * NE + e] = acc[i][j] + bias[e];
            }
        }
    }
}

// ===========================================================================
// Token projection v3: one sync per chunk (R15 pattern)
// ===========================================================================
#define PPITCH 144
#define PBOFF  (128 * PPITCH)
#define PSTAGE (2 * PBOFF)
#define VIS_BX 148
#define TEX_BX 58

__global__ __launch_bounds__(256, 2) void proj_mma2(
    const float* __restrict__ bias_v, const float* __restrict__ bias_t)
{
    const int z = blockIdx.z;
    if (z == 1 && blockIdx.x >= TEX_BX) return;
    const int R = z ? (NQ * NT) : (NB * NV);
    const uint4* Xb = (const uint4*)(z ? g_xtb : g_xvb);
    const uint4* Wb = (const uint4*)(z ? g_wtb : g_wvb);
    const float* bias = z ? bias_t : bias_v;
    float* Y = z ? g_ttok_f32 : g_vtok_f32;

    extern __shared__ __align__(16) char psm[];
    const uint32_t st0 = smem_u32(psm), st1 = st0 + PSTAGE;

    const int tid = threadIdx.x, wid = tid >> 5, lane = tid & 31;
    const int r0 = blockIdx.x * 128, e0 = blockIdx.y * 128;
    const int mrow = (wid & 3) * 32, ncol = (wid >> 2) * 64;

    const uint32_t aoff = (uint32_t)(mrow + (lane & 7) + ((lane >> 3) & 1) * 8) * PPITCH
                        + (uint32_t)(lane >> 4) * 16;
    const uint32_t boff = PBOFF
                        + (uint32_t)(ncol + (lane & 7) + ((lane >> 4) << 3)) * PPITCH
                        + (uint32_t)((lane >> 3) & 1) * 16;

    float c[2][8][4];
#pragma unroll
    for (int mi = 0; mi < 2; mi++)
#pragma unroll
        for (int ni = 0; ni < 8; ni++)
#pragma unroll
            for (int j = 0; j < 4; j++) c[mi][ni][j] = 0.f;

    auto issue = [&](int ch, uint32_t sbase) {
        const int k4 = ch * 8;
#pragma unroll
        for (int it = 0; it < 8; it++) {
            int slot = it * 256 + tid, row = slot >> 3, seg = slot & 7;
            if (row < 128) {
                bool ok = (r0 + row) < R;
                const uint4* src = Xb + (ok ? (size_t)(r0 + row) * 96 : 0) + k4 + seg;
                cp16(sbase + (uint32_t)(row * PPITCH + seg * 16), src, ok);
            } else {
                int wr = row - 128;
                const uint4* src = Wb + (size_t)(e0 + wr) * 96 + k4 + seg;
                cp16(sbase + (uint32_t)(PBOFF + wr * PPITCH + seg * 16), src, true);
            }
        }
    };

    issue(0, st0); CP_COMMIT();

    for (int ch = 0; ch < 12; ch++) {
        asm volatile("cp.async.wait_group 0;" ::: "memory");
        __syncthreads();

        const uint32_t sb = (ch & 1) ? st1 : st0;
        if (ch + 1 < 12) { issue(ch + 1, (ch & 1) ? st0 : st1); CP_COMMIT(); }

        const uint32_t aa = sb + aoff, ba = sb + boff;
#pragma unroll
        for (int ks = 0; ks < 4; ks++) {
            uint32_t af[2][4], bf[16];
#pragma unroll
            for (int mi = 0; mi < 2; mi++)
                ldmatrix_x4(af[mi], aa + mi * (16 * PPITCH) + ks * 32);
#pragma unroll
            for (int nn = 0; nn < 4; nn++)
                ldmatrix_x4(bf + nn * 4, ba + nn * (16 * PPITCH) + ks * 32);
#pragma unroll
            for (int mi = 0; mi < 2; mi++)
#pragma unroll
                for (int ni = 0; ni < 8; ni++)
                    mma_16816(c[mi][ni], af[mi], bf + ni * 2);
        }
    }

#pragma unroll
    for (int mi = 0; mi < 2; mi++) {
        int rr = r0 + mrow + mi * 16 + (lane >> 2);
        if (rr < R) {
#pragma unroll
            for (int ni = 0; ni < 8; ni++) {
                int e = e0 + ncol + ni * 8 + ((lane & 3) << 1);
                float2 o;
                o.x = c[mi][ni][0] + bias[e];
                o.y = c[mi][ni][1] + bias[e + 1];
                *(float2*)(Y + (size_t)rr * NE + e) = o;
                o.x = c[mi][ni][2] + bias[e];
                o.y = c[mi][ni][3] + bias[e + 1];
                *(float2*)(Y + (size_t)(rr + 8) * NE + e) = o;
            }
        }
    }
}

// ===========================================================================
// L2-normalize rows (fp32 in), write bf16 operand buffers
// ===========================================================================
__global__ __launch_bounds__(256) void l2norm_rows()
{
    const int NROWS_V = NB * NV;
    const int NROWS = NROWS_V + NQ * NT;
    int row = blockIdx.x * 8 + (threadIdx.x >> 5);
    int lane = threadIdx.x & 31;
    if (row >= NROWS) return;
    const float* src;
    __nv_bfloat16* dst;
    if (row < NROWS_V) {
        src = g_vtok_f32 + (size_t)row * NE;
        dst = g_vtok + (size_t)row * NE;
    } else {
        src = g_ttok_f32 + (size_t)(row - NROWS_V) * NE;
        dst = g_ttok + (size_t)(row - NROWS_V) * NE;
    }
    const float4* p4 = (const float4*)src;
    float s = 0.f;
#pragma unroll
    for (int i = lane; i < NE / 4; i += 32) {
        float4 v = p4[i];
        s += v.x * v.x + v.y * v.y + v.z * v.z + v.w * v.w;
    }
#pragma unroll
    for (int off = 16; off > 0; off >>= 1)
        s += __shfl_xor_sync(0xffffffffu, s, off);
    float inv = 1.f / fmaxf(sqrtf(s), 1e-12f);
    __nv_bfloat162* d2 = (__nv_bfloat162*)dst;
#pragma unroll
    for (int i = lane; i < NE / 4; i += 32) {
        float4 v = p4[i];
        d2[2 * i]     = __float22bfloat162_rn(make_float2(v.x * inv, v.y * inv));
        d2[2 * i + 1] = __float22bfloat162_rn(make_float2(v.z * inv, v.w * inv));
    }
}

// ===========================================================================
// Stage 2 v6: as v5, with cp.async issue rebalanced onto light warps (5-7).
//   Light warps (mcnt=1, tid>=160, 96 thr): A slots [0,1152) + all B slots.
//   Heavy warps (mcnt=2, tid<160, 160 thr): A slots [1152,1576).
// ===========================================================================
#define APITCH 144
#define MROWS  208
#define BOFF2  (MROWS * APITCH)
#define STAGE  (BOFF2 + 80 * APITCH)
#define SMEM_DYN (2 * STAGE)
#define NINF   (-INFINITY)

__global__ __launch_bounds__(256, 2) void stage2(
    const int* __restrict__ text_length,
    float* __restrict__ t2v, float* __restrict__ v2t)
{
    extern __shared__ __align__(16) char dsm[];
    __shared__ float s_colmax[8][84];
    __shared__ float s_vsum[8];
    __shared__ float s_part[8];

    const int tid = threadIdx.x;
    const int wid = tid >> 5, lane = tid & 31;
    const int q = blockIdx.x, b = blockIdx.y;

    const int len = text_length[q];
    const int nnlim = (len + 15) >> 4;
    const int nrows = nnlim << 4;

    const uint4* Va = (const uint4*)(g_vtok + (size_t)b * NV * NE);
    const uint4* Tt = (const uint4*)(g_ttok + (size_t)q * NT * NE);

    const uint32_t st0 = smem_u32(dsm), st1 = st0 + STAGE;

    const int mcnt = (wid < 5) ? 2 : 1;
    const int moff = (wid < 5) ? wid * 32 : 160 + (wid - 5) * 16;
    const bool has2 = (mcnt == 2);

    const uint32_t aoff = (uint32_t)(moff + (lane & 7) + ((lane >> 3) & 1) * 8) * APITCH
                        + (uint32_t)(lane >> 4) * 16;
    const uint32_t boff = BOFF2
                        + (uint32_t)((lane & 7) + ((lane >> 4) << 3)) * APITCH
                        + (uint32_t)((lane >> 3) & 1) * 16;

    float c[2][10][4];
#pragma unroll
    for (int mi = 0; mi < 2; mi++)
#pragma unroll
        for (int ni = 0; ni < 10; ni++)
#pragma unroll
            for (int j = 0; j < 4; j++) c[mi][ni][j] = 0.f;

    // Weighted cp.async issue: light warps (tid >= 160) carry most of it.
    auto issue = [&](int ch, uint32_t sbase) {
        const int k4 = ch * 8;
        if (tid >= 160) {                          // 96 light threads
            const int l = tid - 160;
#pragma unroll
            for (int it = 0; it < 12; it++) {      // A slots 0..1151 (rows 0..143)
                int slot = it * 96 + l;
                int row = slot >> 3, seg = slot & 7;
                cp16(sbase + (uint32_t)(row * APITCH + seg * 16),
                     Va + row * 64 + k4 + seg, true);
            }
#pragma unroll
            for (int it = 0; it < 7; it++) {       // all B slots 0..639
                int slot = it * 96 + l;
                if (slot < 640) {
                    int row = slot >> 3, seg = slot & 7;
                    if (row < nrows) {
                        bool ok = row < NT;
                        const uint4* src = Tt + (ok ? row * 64 : 0) + k4 + seg;
                        cp16(sbase + (uint32_t)(BOFF2 + row * APITCH + seg * 16),
                             src, ok);
                    }
                }
            }
        } else {                                   // 160 heavy threads
#pragma unroll
            for (int it = 0; it < 3; it++) {       // A slots 1152..1575
                int slot = 1152 + it * 160 + tid;
                if (slot < NV * 8) {
                    int row = slot >> 3, seg = slot & 7;
                    cp16(sbase + (uint32_t)(row * APITCH + seg * 16),
                         Va + row * 64 + k4 + seg, true);
                }
            }
        }
    };

    issue(0, st0); CP_COMMIT();

    for (int ch = 0; ch < 8; ch++) {
        asm volatile("cp.async.wait_group 0;" ::: "memory");
        __syncthreads();

        const uint32_t sb = (ch & 1) ? st1 : st0;
        if (ch + 1 < 8) { issue(ch + 1, (ch & 1) ? st0 : st1); CP_COMMIT(); }

        const uint32_t aa = sb + aoff, ba = sb + boff;
#pragma unroll
        for (int ks = 0; ks < 4; ks++) {
            uint32_t af[2][4], bf[20];
            ldmatrix_x4(af[0], aa + ks * 32);
            if (has2) ldmatrix_x4(af[1], aa + 16 * APITCH + ks * 32);
#pragma unroll
            for (int nn = 0; nn < 5; nn++)
                if (nn < nnlim)
                    ldmatrix_x4(bf + nn * 4, ba + nn * (16 * APITCH) + ks * 32);
#pragma unroll
            for (int ni = 0; ni < 10; ni++)
                if (ni < 2 * nnlim)
                    mma_16816(c[0][ni], af[0], bf + ni * 2);
            if (has2) {
#pragma unroll
                for (int ni = 0; ni < 10; ni++)
                    if (ni < 2 * nnlim)
                        mma_16816(c[1][ni], af[1], bf + ni * 2);
            }
        }
    }

    // ---- register/shfl epilogue ----
    const int rb = moff + (lane >> 2);

    float rowmax[2][2] = {{NINF, NINF}, {NINF, NINF}};
    float colmax[10][2];
#pragma unroll
    for (int ni = 0; ni < 10; ni++) { colmax[ni][0] = NINF; colmax[ni][1] = NINF; }

#pragma unroll
    for (int mi = 0; mi < 2; mi++) {
        const bool active = (mi == 0) || has2;
        int r0 = rb + mi * 16;
        bool v0 = active && (r0 < NV), v8 = active && ((r0 + 8) < NV);
#pragma unroll
        for (int ni = 0; ni < 10; ni++) {
            int tl = ni * 8 + ((lane & 3) << 1);
            float* cf = c[mi][ni];
            float m0 = (tl     < len) ? cf[0] : ((tl     < NT) ? 0.f : NINF);
            float m1 = (tl + 1 < len) ? cf[1] : ((tl + 1 < NT) ? 0.f : NINF);
            float m2 = (tl     < len) ? cf[2] : ((tl     < NT) ? 0.f : NINF);
            float m3 = (tl + 1 < len) ? cf[3] : ((tl + 1 < NT) ? 0.f : NINF);
            rowmax[mi][0] = fmaxf(rowmax[mi][0], fmaxf(m0, m1));
            rowmax[mi][1] = fmaxf(rowmax[mi][1], fmaxf(m2, m3));
            colmax[ni][0] = fmaxf(colmax[ni][0],
                fmaxf(v0 ? cf[0] : NINF, v8 ? cf[2] : NINF));
            colmax[ni][1] = fmaxf(colmax[ni][1],
                fmaxf(v0 ? cf[1] : NINF, v8 ? cf[3] : NINF));
        }
    }

#pragma unroll
    for (int mi = 0; mi < 2; mi++)
#pragma unroll
        for (int h = 0; h < 2; h++) {
            float r = rowmax[mi][h];
            r = fmaxf(r, __shfl_xor_sync(0xffffffffu, r, 1));
            r = fmaxf(r, __shfl_xor_sync(0xffffffffu, r, 2));
            rowmax[mi][h] = r;
        }
    float rowsum = 0.f;
#pragma unroll
    for (int mi = 0; mi < 2; mi++) {
        const bool active = (mi == 0) || has2;
        int r0 = rb + mi * 16;
        if (active && r0 < NV)       rowsum += rowmax[mi][0];
        if (active && (r0 + 8) < NV) rowsum += rowmax[mi][1];
    }
    rowsum += __shfl_xor_sync(0xffffffffu, rowsum, 4);
    rowsum += __shfl_xor_sync(0xffffffffu, rowsum, 8);
    rowsum += __shfl_xor_sync(0xffffffffu, rowsum, 16);
    if (lane == 0) s_vsum[wid] = rowsum;

#pragma unroll
    for (int ni = 0; ni < 10; ni++)
#pragma unroll
        for (int h = 0; h < 2; h++) {
            float r = colmax[ni][h];
            r = fmaxf(r, __shfl_xor_sync(0xffffffffu, r, 4));
            r = fmaxf(r, __shfl_xor_sync(0xffffffffu, r, 8));
            r = fmaxf(r, __shfl_xor_sync(0xffffffffu, r, 16));
            colmax[ni][h] = r;
        }
    if (lane < 4) {
#pragma unroll
        for (int ni = 0; ni < 10; ni++) {
            int cc = ni * 8 + (lane << 1);
            s_colmax[wid][cc]     = colmax[ni][0];
            s_colmax[wid][cc + 1] = colmax[ni][1];
        }
    }
    __syncthreads();

    float val = 0.f;
    if (tid < 80) {
        float cm = NINF;
#pragma unroll
        for (int w = 0; w < 8; w++) cm = fmaxf(cm, s_colmax[w][tid]);
        val = (tid < len) ? cm : 0.f;
    }
#pragma unroll
    for (int off = 16; off > 0; off >>= 1)
        val += __shfl_xor_sync(0xffffffffu, val, off);
    if (lane == 0) s_part[wid] = val;
    __syncthreads();

    if (tid == 0) {
        float ts = s_part[0] + s_part[1] + s_part[2] + s_part[3];
        float vs = 0.f;
#pragma unroll
        for (int w = 0; w < 8; w++) vs += s_vsum[w];
        t2v[b * NQ + q] = ts / (float)len;
        v2t[b * NQ + q] = vs / (float)NV;
    }
}

// ===========================================================================
extern "C" void kernel_launch(void* const* d_in, const int* in_sizes, int n_in,
                              void* d_out, int out_size)
{
    const float* visual_cls     = (const float*)d_in[0];
    const float* visual_tokens  = (const float*)d_in[1];
    const float* textual_cls    = (const float*)d_in[2];
    const float* textual_tokens = (const float*)d_in[3];
    const float* Wv_cls = (const float*)d_in[4];
    const float* bv_cls = (const float*)d_in[5];
    const float* Wt_cls = (const float*)d_in[6];
    const float* bt_cls = (const float*)d_in[7];
    const float* Wv_tok = (const float*)d_in[8];
    const float* bv_tok = (const float*)d_in[9];
    const float* Wt_tok = (const float*)d_in[10];
    const float* bt_tok = (const float*)d_in[11];
    const int*   text_length = (const int*)d_in[12];

    float* out = (float*)d_out;
    float* o_vcls = out;
    float* o_tcls = out + NB * NE;
    float* o_t2v  = out + 2 * NB * NE;
    float* o_v2t  = o_t2v + NB * NQ;

    static cudaStream_t s2 = nullptr;
    static cudaEvent_t ev_fork = nullptr, ev_join = nullptr;
    if (s2 == nullptr) {
        cudaStreamCreateWithFlags(&s2, cudaStreamNonBlocking);
        cudaEventCreateWithFlags(&ev_fork, cudaEventDisableTiming);
        cudaEventCreateWithFlags(&ev_join, cudaEventDisableTiming);
    }

    // Fork: independent cls projections on side stream
    cudaEventRecord(ev_fork, 0);
    cudaStreamWaitEvent(s2, ev_fork, 0);
    proj_cls<<<dim3(2, 8, 2), 256, 0, s2>>>(visual_cls, Wv_cls, bv_cls, o_vcls,
                                            textual_cls, Wt_cls, bt_cls, o_tcls);
    cudaEventRecord(ev_join, s2);

    // Main chain
    {
        size_t n8 = CSEG3 / 8;
        int blocks = (int)((n8 + 255) / 256);
        convert_bf16<<<blocks, 256>>>(visual_tokens, textual_tokens, Wv_tok, Wt_tok);
    }

    cudaFuncSetAttribute(proj_mma2, cudaFuncAttributeMaxDynamicSharedMemorySize,
                         2 * PSTAGE);
    proj_mma2<<<dim3(VIS_BX, 4, 2), 256, 2 * PSTAGE>>>(bv_tok, bt_tok);

    l2norm_rows<<<(NB * NV + NQ * NT + 7) / 8, 256>>>();

    cudaFuncSetAttribute(stage2, cudaFuncAttributeMaxDynamicSharedMemorySize, SMEM_DYN);
    stage2<<<dim3(NQ, NB), 256, SMEM_DYN>>>(text_length, o_t2v, o_v2t);

    cudaStreamWaitEvent(0, ev_join, 0);
}